// round 6
// baseline (speedup 1.0000x reference)
#include <cuda_runtime.h>
#include <cstdint>
#include <cstddef>

// Problem constants
#define BB 512
#define TT 512
#define FF 64
#define PP 32
#define UU 512
#define LL 3

// Kernel config
#define CS   2                 // cluster size (CTAs)
#define RR   8                 // batch rows per cluster
#define HALF 256               // output columns per CTA (UU / CS)
#define NTH  256               // threads: 128 col-pairs x 2 row-halves
#define NCTA ((BB / RR) * CS)  // 128 CTAs = 64 clusters

typedef unsigned long long u64;

// ---------------- packed f32x2 helpers ----------------
__device__ __forceinline__ void fma2(u64& d, u64 a, u64 b) {
    asm("fma.rn.f32x2 %0, %1, %2, %0;" : "+l"(d) : "l"(a), "l"(b));
}
__device__ __forceinline__ u64 pack2(float x, float y) {
    u64 r;
    asm("mov.b64 %0, {%1, %2};" : "=l"(r)
        : "r"(__float_as_uint(x)), "r"(__float_as_uint(y)));
    return r;
}

// ---------------- cluster helpers ----------------
__device__ __forceinline__ void cluster_sync() {
    asm volatile("barrier.cluster.arrive.aligned;" ::: "memory");
    asm volatile("barrier.cluster.wait.aligned;" ::: "memory");
}
__device__ __forceinline__ unsigned ctarank() {
    unsigned r; asm("mov.u32 %0, %%cluster_ctarank;" : "=r"(r)); return r;
}
__device__ __forceinline__ unsigned mapa_u32(unsigned addr, unsigned rank) {
    unsigned r;
    asm("mapa.shared::cluster.u32 %0, %1, %2;" : "=r"(r) : "r"(addr), "r"(rank));
    return r;
}
__device__ __forceinline__ void st_cluster_u64(unsigned raddr, u64 v) {
    asm volatile("st.shared::cluster.u64 [%0], %1;" :: "r"(raddr), "l"(v));
}

// Accumulating mat-vec slice. Thread owns 2 columns (cp2, cp2+1 within this
// CTA's HALF-col slice) x 4 rows (rh4..rh4+3). Weights direct LDG from L2
// (each warp: one 128B line per k). Activations act[k][RR] in smem, LDS.128.
// acc[cc][j]: column cc, row-pair j.
template<int K>
__device__ __forceinline__ void mv(u64 acc[2][2], const float* __restrict__ Wg,
                                   const float* __restrict__ act, int cp2, int rh4)
{
#pragma unroll 16
    for (int k = 0; k < K; ++k) {
        float2 w = *reinterpret_cast<const float2*>(Wg + (size_t)k * UU + cp2);
        ulonglong2 a = *reinterpret_cast<const ulonglong2*>(act + k * RR + rh4);
        u64 wx = pack2(w.x, w.x);
        u64 wy = pack2(w.y, w.y);
        fma2(acc[0][0], a.x, wx); fma2(acc[0][1], a.y, wx);
        fma2(acc[1][0], a.x, wy); fma2(acc[1][1], a.y, wy);
    }
}

// Write 2 cols x 4 rows to local buffer + peer CTA's mirror (DSMEM).
__device__ __forceinline__ void writeback(const u64 acc[2][2], float* lbuf,
                                          unsigned rbuf, int c0, int rh4)
{
#pragma unroll
    for (int cc = 0; cc < 2; ++cc) {
        int c = c0 + cc;
        u64* d = reinterpret_cast<u64*>(lbuf + c * RR + rh4);
        d[0] = acc[cc][0];
        d[1] = acc[cc][1];
        unsigned ra = rbuf + (unsigned)((c * RR + rh4) * sizeof(float));
        st_cluster_u64(ra,     acc[cc][0]);
        st_cluster_u64(ra + 8, acc[cc][1]);
    }
}

// Shared memory layout (floats)
#define SM_HS    0                        // LL*UU*RR = 12288   ([layer][col][row])
#define SM_PREV  (SM_HS   + LL*UU*RR)     // UU*RR    = 4096    ([col][row])
#define SM_IN96  (SM_PREV + UU*RR)        // (FF+PP)*RR = 768   ([k][row]; tail = running acc)
#define SM_WOUT  (SM_IN96 + (FF+PP)*RR)   // UU*PP    = 16384
#define SM_BAB   (SM_WOUT + UU*PP)        // LL*HALF  = 768  (bA+bB, own col slice)
#define SM_BC    (SM_BAB  + LL*HALF)      // LL*HALF  = 768
#define SM_BOUT  (SM_BC   + LL*HALF)      // PP       = 32
#define SM_TOTAL (SM_BOUT + PP)           // 35104 floats = 140416 B

extern "C" __global__ void __launch_bounds__(NTH, 1) __cluster_dims__(CS, 1, 1)
accrnn_kernel(const float* __restrict__ x,
              const float* __restrict__ WA,  const float* __restrict__ bA,
              const float* __restrict__ WB0, const float* __restrict__ bB0,
              const float* __restrict__ WBr, const float* __restrict__ bBr,
              const float* __restrict__ WC,  const float* __restrict__ bC,
              const float* __restrict__ Wout, const float* __restrict__ bout,
              float* __restrict__ out)
{
    extern __shared__ __align__(16) float sm[];
    float* hs    = sm + SM_HS;
    float* prev  = sm + SM_PREV;
    float* in96  = sm + SM_IN96;
    float* wouts = sm + SM_WOUT;
    float* sAB   = sm + SM_BAB;
    float* sC    = sm + SM_BC;
    float* sout  = sm + SM_BOUT;

    const int tid  = threadIdx.x;
    const int cp2  = (tid >> 1) * 2;       // column pair base within slice
    const int rh4  = (tid & 1) * 4;        // row-half base
    const unsigned rank  = ctarank();
    const unsigned prank = rank ^ 1u;
    const int row0 = (blockIdx.x / CS) * RR;
    const int coff = (int)rank * HALF;
    const int c0   = coff + cp2;           // absolute column base

    const unsigned sbase = (unsigned)__cvta_generic_to_shared(sm);
    const unsigned rbase = mapa_u32(sbase, prank);
    const unsigned rprev = rbase + (unsigned)(SM_PREV * sizeof(float));

    // ---- one-time preload ----
    for (int i = tid; i < UU * PP; i += NTH) wouts[i] = Wout[i];
    for (int l = 0; l < LL; ++l)
        for (int j = tid; j < HALF; j += NTH) {
            int c = coff + j;
            sAB[l * HALF + j] = bA[l * UU + c] + (l == 0 ? bB0[c] : bBr[(l - 1) * UU + c]);
            sC[l * HALF + j]  = bC[l * UU + c];
        }
    if (tid < PP) sout[tid] = bout[tid];
    for (int i = tid; i < LL * UU * RR; i += NTH) hs[i] = 0.f;
    for (int i = tid; i < (FF + PP) * RR; i += NTH) in96[i] = 0.f;
    __syncthreads();
    cluster_sync();

    for (int t = 0; t < TT; ++t) {
        // ---- x part of concat input, layout [f][row] ----
#pragma unroll
        for (int j = 0; j < (RR * FF) / NTH; ++j) {
            int idx = tid + j * NTH;
            int f = idx & 63, r = idx >> 6;
            in96[f * RR + r] = x[((size_t)(row0 + r) * TT + t) * FF + f];
        }
        __syncthreads();   // also covers prior-step tail (acc) writes

        const float* actB = in96;

        for (int l = 0; l < LL; ++l) {
            // ---- new_state slice = hs_l @ WA_l + actB @ WB_l + biases ----
            u64 acc[2][2];
            {
                float b0 = sAB[l * HALF + cp2];
                float b1 = sAB[l * HALF + cp2 + 1];
                acc[0][0] = acc[0][1] = pack2(b0, b0);
                acc[1][0] = acc[1][1] = pack2(b1, b1);
            }
            float* hl = hs + l * UU * RR;
            mv<UU>(acc, WA + (size_t)l * UU * UU + coff, hl, cp2, rh4);
            if (l == 0) mv<FF + PP>(acc, WB0 + coff, actB, cp2, rh4);
            else        mv<UU>(acc, WBr + (size_t)(l - 1) * UU * UU + coff, actB, cp2, rh4);

            cluster_sync();   // all reads of hs_l / actB complete cluster-wide
            writeback(acc, hl,
                      rbase + (unsigned)((SM_HS + l * UU * RR) * sizeof(float)),
                      c0, rh4);
            cluster_sync();   // new hs_l visible in both CTAs

            // ---- prev slice = new_state @ WC_l + bC_l ----
            u64 acc2[2][2];
            {
                float b0 = sC[l * HALF + cp2];
                float b1 = sC[l * HALF + cp2 + 1];
                acc2[0][0] = acc2[0][1] = pack2(b0, b0);
                acc2[1][0] = acc2[1][1] = pack2(b1, b1);
            }
            mv<UU>(acc2, WC + (size_t)l * UU * UU + coff, hl, cp2, rh4);
            writeback(acc2, prev, rprev, c0, rh4);
            cluster_sync();   // prev visible in both CTAs

            actB = prev;
        }

        // ---- res = prev @ Wout + bout ; acc += res ; store res ----
        {
            int r = tid >> 5, p = tid & 31;
            float s0 = sout[p], s1 = 0.f;
#pragma unroll 8
            for (int k = 0; k < UU; k += 2) {
                s0 = fmaf(prev[k * RR + r],       wouts[k * PP + p],       s0);
                s1 = fmaf(prev[(k + 1) * RR + r], wouts[(k + 1) * PP + p], s1);
            }
            float res = s0 + s1;
            in96[(FF + p) * RR + r] += res;   // running accumulator (concat tail)
            if (rank == 0)
                out[((size_t)(row0 + r) * TT + t) * PP + p] = res;
        }
        // next iteration's __syncthreads orders tail writes before layer-0 reads
    }
}

extern "C" void kernel_launch(void* const* d_in, const int* in_sizes, int n_in,
                              void* d_out, int out_size)
{
    const float* x    = (const float*)d_in[0];
    const float* WA   = (const float*)d_in[1];
    const float* bA   = (const float*)d_in[2];
    const float* WB0  = (const float*)d_in[3];
    const float* bB0  = (const float*)d_in[4];
    const float* WBr  = (const float*)d_in[5];
    const float* bBr  = (const float*)d_in[6];
    const float* WC   = (const float*)d_in[7];
    const float* bC   = (const float*)d_in[8];
    const float* Wout = (const float*)d_in[9];
    const float* bout = (const float*)d_in[10];
    float* out = (float*)d_out;

    size_t smem = (size_t)SM_TOTAL * sizeof(float);
    cudaFuncSetAttribute(accrnn_kernel, cudaFuncAttributeMaxDynamicSharedMemorySize, (int)smem);
    accrnn_kernel<<<NCTA, NTH, smem>>>(x, WA, bA, WB0, bB0, WBr, bBr, WC, bC, Wout, bout, out);
}

// round 7
// speedup vs baseline: 1.0152x; 1.0152x over previous
#include <cuda_runtime.h>
#include <cstdint>
#include <cstddef>

// Problem constants
#define BB 512
#define TT 512
#define FF 64
#define PP 32
#define UU 512
#define LL 3

// Kernel config
#define CS   2                 // cluster size (CTAs)
#define RR   8                 // batch rows per cluster
#define HALF 256               // output columns per CTA (UU / CS)
#define NTH  512               // 128 col-pairs x 2 row-halves x 2 k-halves
#define NCTA ((BB / RR) * CS)  // 128 CTAs = 64 clusters

typedef unsigned long long u64;

// ---------------- packed f32x2 helpers ----------------
__device__ __forceinline__ void fma2(u64& d, u64 a, u64 b) {
    asm("fma.rn.f32x2 %0, %1, %2, %0;" : "+l"(d) : "l"(a), "l"(b));
}
__device__ __forceinline__ u64 pack2(float x, float y) {
    u64 r;
    asm("mov.b64 %0, {%1, %2};" : "=l"(r)
        : "r"(__float_as_uint(x)), "r"(__float_as_uint(y)));
    return r;
}

// ---------------- cluster helpers ----------------
__device__ __forceinline__ void cluster_sync() {
    asm volatile("barrier.cluster.arrive.aligned;" ::: "memory");
    asm volatile("barrier.cluster.wait.aligned;" ::: "memory");
}
__device__ __forceinline__ unsigned ctarank() {
    unsigned r; asm("mov.u32 %0, %%cluster_ctarank;" : "=r"(r)); return r;
}
__device__ __forceinline__ unsigned mapa_u32(unsigned addr, unsigned rank) {
    unsigned r;
    asm("mapa.shared::cluster.u32 %0, %1, %2;" : "=r"(r) : "r"(addr), "r"(rank));
    return r;
}
__device__ __forceinline__ void st_cluster_u64(unsigned raddr, u64 v) {
    asm volatile("st.shared::cluster.u64 [%0], %1;" :: "r"(raddr), "l"(v));
}

// Accumulating mat-vec slice over HALF the k-range.
// Thread: 2 cols (cp2, cp2+1) x 4 rows (rh4..rh4+3), k in [k0, k0+K/2).
template<int K>
__device__ __forceinline__ void mv(u64 acc[2][2], const float* __restrict__ Wg,
                                   const float* __restrict__ act,
                                   int cp2, int rh4, int k0)
{
    const float* W = Wg + (size_t)k0 * UU;
    const float* A = act + k0 * RR;
#pragma unroll 16
    for (int k = 0; k < K / 2; ++k) {
        float2 w = *reinterpret_cast<const float2*>(W + (size_t)k * UU + cp2);
        ulonglong2 a = *reinterpret_cast<const ulonglong2*>(A + k * RR + rh4);
        u64 wx = pack2(w.x, w.x);
        u64 wy = pack2(w.y, w.y);
        fma2(acc[0][0], a.x, wx); fma2(acc[0][1], a.y, wx);
        fma2(acc[1][0], a.x, wy); fma2(acc[1][1], a.y, wy);
    }
}

// k-half reduction through smem scratch (stride 5 u64 per slot to dodge conflicts).
// kh==1 stores partials; after __syncthreads, kh==0 folds them in.
#define SLOT_U64 5
__device__ __forceinline__ void red_store(const u64 acc[2][2], u64* scr, int slot) {
    u64* s = scr + slot * SLOT_U64;
    s[0] = acc[0][0]; s[1] = acc[0][1]; s[2] = acc[1][0]; s[3] = acc[1][1];
}
__device__ __forceinline__ void red_fold(u64 acc[2][2], const u64* scr, int slot, u64 one) {
    const u64* s = scr + slot * SLOT_U64;
    fma2(acc[0][0], s[0], one); fma2(acc[0][1], s[1], one);
    fma2(acc[1][0], s[2], one); fma2(acc[1][1], s[3], one);
}

// Write 2 cols x 4 rows to local buffer + peer CTA mirror (DSMEM).
__device__ __forceinline__ void writeback(const u64 acc[2][2], float* lbuf,
                                          unsigned rbuf, int c0, int rh4)
{
#pragma unroll
    for (int cc = 0; cc < 2; ++cc) {
        int c = c0 + cc;
        u64* d = reinterpret_cast<u64*>(lbuf + c * RR + rh4);
        d[0] = acc[cc][0];
        d[1] = acc[cc][1];
        unsigned ra = rbuf + (unsigned)((c * RR + rh4) * sizeof(float));
        st_cluster_u64(ra,     acc[cc][0]);
        st_cluster_u64(ra + 8, acc[cc][1]);
    }
}

// Shared memory layout (floats)
#define SM_HS    0                        // LL*UU*RR = 12288   ([layer][col][row])
#define SM_PREV  (SM_HS   + LL*UU*RR)     // UU*RR    = 4096    ([col][row])
#define SM_IN96  (SM_PREV + UU*RR)        // (FF+PP)*RR = 768
#define SM_SCR   (SM_IN96 + (FF+PP)*RR)   // 256*SLOT_U64*2 = 2560
#define SM_TSCR  (SM_SCR  + 256*SLOT_U64*2) // 256
#define SM_BAB   (SM_TSCR + 256)          // LL*HALF = 768
#define SM_BC    (SM_BAB  + LL*HALF)      // LL*HALF = 768
#define SM_BOUT  (SM_BC   + LL*HALF)      // PP = 32
#define SM_TOTAL (SM_BOUT + PP)           // 21536 floats = 86144 B

extern "C" __global__ void __launch_bounds__(NTH, 1) __cluster_dims__(CS, 1, 1)
accrnn_kernel(const float* __restrict__ x,
              const float* __restrict__ WA,  const float* __restrict__ bA,
              const float* __restrict__ WB0, const float* __restrict__ bB0,
              const float* __restrict__ WBr, const float* __restrict__ bBr,
              const float* __restrict__ WC,  const float* __restrict__ bC,
              const float* __restrict__ Wout, const float* __restrict__ bout,
              float* __restrict__ out)
{
    extern __shared__ __align__(16) float sm[];
    float* hs   = sm + SM_HS;
    float* prev = sm + SM_PREV;
    float* in96 = sm + SM_IN96;
    u64*   scr  = reinterpret_cast<u64*>(sm + SM_SCR);
    float* tscr = sm + SM_TSCR;
    float* sAB  = sm + SM_BAB;
    float* sC   = sm + SM_BC;
    float* sout = sm + SM_BOUT;

    const int tid  = threadIdx.x;
    const int lane = tid & 31;
    const int wrp  = tid >> 5;            // 0..15
    const int rh4  = (lane & 1) * 4;      // row-half base
    const int kh   = wrp >> 3;            // k-half
    const int cp2  = (((wrp & 7) * 16) + (lane >> 1)) * 2;  // col-pair base in slice
    const int slot = cp2 + (rh4 >> 2);    // 0..255 unique per (cp2, rh)

    const unsigned rank  = ctarank();
    const unsigned prank = rank ^ 1u;
    const int row0 = (blockIdx.x / CS) * RR;
    const int coff = (int)rank * HALF;
    const int c0   = coff + cp2;
    const u64 ONE  = pack2(1.f, 1.f);

    const unsigned sbase = (unsigned)__cvta_generic_to_shared(sm);
    const unsigned rbase = mapa_u32(sbase, prank);
    const unsigned rprev = rbase + (unsigned)(SM_PREV * sizeof(float));

    // ---- one-time preload ----
    for (int l = 0; l < LL; ++l)
        for (int j = tid; j < HALF; j += NTH) {
            int c = coff + j;
            sAB[l * HALF + j] = bA[l * UU + c] + (l == 0 ? bB0[c] : bBr[(l - 1) * UU + c]);
            sC[l * HALF + j]  = bC[l * UU + c];
        }
    if (tid < PP) sout[tid] = bout[tid];
    for (int i = tid; i < LL * UU * RR; i += NTH) hs[i] = 0.f;
    for (int i = tid; i < (FF + PP) * RR; i += NTH) in96[i] = 0.f;
    __syncthreads();
    cluster_sync();

    for (int t = 0; t < TT; ++t) {
        // ---- x part of concat input, layout [f][row] ---- (RR*FF == NTH)
        {
            int f = tid & 63, r = tid >> 6;
            in96[f * RR + r] = x[((size_t)(row0 + r) * TT + t) * FF + f];
        }
        __syncthreads();   // also orders prior-step acc-tail writes

        const float* actB = in96;

        for (int l = 0; l < LL; ++l) {
            // ---- new_state slice = hs_l @ WA_l + actB @ WB_l + biases ----
            u64 acc[2][2];
            if (kh == 0) {
                float b0 = sAB[l * HALF + cp2];
                float b1 = sAB[l * HALF + cp2 + 1];
                acc[0][0] = acc[0][1] = pack2(b0, b0);
                acc[1][0] = acc[1][1] = pack2(b1, b1);
            } else {
                acc[0][0] = acc[0][1] = acc[1][0] = acc[1][1] = 0ull;
            }
            float* hl = hs + l * UU * RR;
            mv<UU>(acc, WA + (size_t)l * UU * UU + coff, hl, cp2, rh4, kh * (UU / 2));
            if (l == 0) mv<FF + PP>(acc, WB0 + coff, actB, cp2, rh4, kh * ((FF + PP) / 2));
            else        mv<UU>(acc, WBr + (size_t)(l - 1) * UU * UU + coff, actB, cp2, rh4, kh * (UU / 2));

            if (kh) red_store(acc, scr, slot);
            __syncthreads();
            if (!kh) red_fold(acc, scr, slot, ONE);

            cluster_sync();   // all reads of hs_l / actB complete cluster-wide
            if (!kh)
                writeback(acc, hl,
                          rbase + (unsigned)((SM_HS + l * UU * RR) * sizeof(float)),
                          c0, rh4);
            cluster_sync();   // new hs_l visible in both CTAs

            // ---- prev slice = new_state @ WC_l + bC_l ----
            u64 acc2[2][2];
            if (kh == 0) {
                float b0 = sC[l * HALF + cp2];
                float b1 = sC[l * HALF + cp2 + 1];
                acc2[0][0] = acc2[0][1] = pack2(b0, b0);
                acc2[1][0] = acc2[1][1] = pack2(b1, b1);
            } else {
                acc2[0][0] = acc2[0][1] = acc2[1][0] = acc2[1][1] = 0ull;
            }
            mv<UU>(acc2, WC + (size_t)l * UU * UU + coff, hl, cp2, rh4, kh * (UU / 2));

            if (kh) red_store(acc2, scr, slot);
            __syncthreads();
            if (!kh) {
                red_fold(acc2, scr, slot, ONE);
                writeback(acc2, prev, rprev, c0, rh4);
            }
            cluster_sync();   // prev visible in both CTAs

            actB = prev;
        }

        // ---- res = prev @ Wout + bout ; acc += res ; store res ----
        {
            int p = tid & 31, r = (tid >> 5) & 7, th = tid >> 8;
            float s0 = th ? 0.f : sout[p], s1 = 0.f;
            int kb = th * (UU / 2);
#pragma unroll 8
            for (int k = 0; k < UU / 2; k += 2) {
                s0 = fmaf(prev[(kb + k) * RR + r],     Wout[(size_t)(kb + k) * PP + p],     s0);
                s1 = fmaf(prev[(kb + k + 1) * RR + r], Wout[(size_t)(kb + k + 1) * PP + p], s1);
            }
            float s = s0 + s1;
            if (th) tscr[r * PP + p] = s;
            __syncthreads();
            if (!th) {
                float res = s + tscr[r * PP + p];
                in96[(FF + p) * RR + r] += res;   // running accumulator (concat tail)
                if (rank == 0)
                    out[((size_t)(row0 + r) * TT + t) * PP + p] = res;
            }
        }
        // next iteration's __syncthreads orders tail writes before layer-0 reads
    }
}

extern "C" void kernel_launch(void* const* d_in, const int* in_sizes, int n_in,
                              void* d_out, int out_size)
{
    const float* x    = (const float*)d_in[0];
    const float* WA   = (const float*)d_in[1];
    const float* bA   = (const float*)d_in[2];
    const float* WB0  = (const float*)d_in[3];
    const float* bB0  = (const float*)d_in[4];
    const float* WBr  = (const float*)d_in[5];
    const float* bBr  = (const float*)d_in[6];
    const float* WC   = (const float*)d_in[7];
    const float* bC   = (const float*)d_in[8];
    const float* Wout = (const float*)d_in[9];
    const float* bout = (const float*)d_in[10];
    float* out = (float*)d_out;

    size_t smem = (size_t)SM_TOTAL * sizeof(float);
    cudaFuncSetAttribute(accrnn_kernel, cudaFuncAttributeMaxDynamicSharedMemorySize, (int)smem);
    accrnn_kernel<<<NCTA, NTH, smem>>>(x, WA, bA, WB0, bB0, WBr, bBr, WC, bC, Wout, bout, out);
}

// round 8
// speedup vs baseline: 3.5615x; 3.5083x over previous
#include <cuda_runtime.h>
#include <cstdint>
#include <cstddef>

// Problem constants
#define BB 512
#define TT 512
#define FF 64
#define PP 32
#define UU 512

// Affine-state formulation
#define ZP  1600          // padded state dim [h1|h2|h3|acc|1|pad]
#define HOM 1568          // homogeneous-one index
#define CH  32            // chunk length
#define NCH (TT/CH)       // 16 chunks
#define XCW (CH*FF)       // 2048 : x columns per chunk
#define ACW (CH*PP)       // 1024 : acc columns per chunk
#define PW  ((CH+1)*PP)   // 1056 : Pstack width (P_0..P_32)

typedef unsigned long long u64;

// ---------------- device scratch (static, no allocs) ----------------
__device__ float gM[ZP*ZP], gM2[ZP*ZP], gM4[ZP*ZP], gM8[ZP*ZP], gM16[ZP*ZP];
__device__ float gN[64*ZP];
__device__ float gT1[ZP*UU];
__device__ float gT2[64*UU];
__device__ float gP[ZP*PW];
__device__ float gV[XCW*ZP];
__device__ float gQ[XCW*ZP];
__device__ float gRs[64*ACW];
__device__ float gH[XCW*ACW];
__device__ float gA[BB*ACW];
__device__ float gZ0[BB*ZP], gZ1[BB*ZP];

// ---------------- packed f32x2 helpers ----------------
__device__ __forceinline__ void fma2(u64& d, u64 a, u64 b) {
    asm("fma.rn.f32x2 %0, %1, %2, %0;" : "+l"(d) : "l"(a), "l"(b));
}
__device__ __forceinline__ u64 pack2(float x, float y) {
    u64 r;
    asm("mov.b64 %0, {%1, %2};" : "=l"(r)
        : "r"(__float_as_uint(x)), "r"(__float_as_uint(y)));
    return r;
}
__device__ __forceinline__ u64 pack2s(float x) {
    u64 r;
    asm("mov.b64 %0, {%1, %1};" : "=l"(r) : "r"(__float_as_uint(x)));
    return r;
}

// ---------------- generic fp32 GEMM: C = A*B (+C if accum) ----------------
// Row-major, runtime leading dims. M,N edge-guarded; K must be mult of 16.
#define BM 64
#define BN 64
#define BK 16

__global__ void __launch_bounds__(128) gemm_k(
    const float* __restrict__ A, int lda,
    const float* __restrict__ B, int ldb,
    float* __restrict__ C, int ldc,
    int M, int N, int K, int accum)
{
    __shared__ float As[2][BK][BM + 4];
    __shared__ float Bs[2][BK][BN];
    const int tid = threadIdx.x;
    const int m0 = blockIdx.y * BM, n0 = blockIdx.x * BN;
    const int tc = tid & 7, tr = tid >> 3;

    int am[2], ak[2], bk_[2], bn[2];
#pragma unroll
    for (int q = 0; q < 2; ++q) {
        int id = tid * 2 + q;
        am[q] = id >> 2;  ak[q] = (id & 3) * 4;
        bk_[q] = id >> 4; bn[q] = (id & 15) * 4;
    }

    u64 acc[4][4];
#pragma unroll
    for (int r = 0; r < 4; ++r)
#pragma unroll
        for (int c = 0; c < 4; ++c) acc[r][c] = 0ull;
    if (accum) {
#pragma unroll
        for (int r = 0; r < 4; ++r)
#pragma unroll
        for (int c = 0; c < 4; ++c) {
            int row = m0 + 4 * tr + r, col = n0 + 8 * tc + 2 * c;
            if (row < M && col < N) {
                float2 v = *reinterpret_cast<const float2*>(&C[(size_t)row * ldc + col]);
                acc[r][c] = pack2(v.x, v.y);
            }
        }
    }

    const float4 z4 = make_float4(0.f, 0.f, 0.f, 0.f);
    float4 pa[2], pb[2];
#pragma unroll
    for (int q = 0; q < 2; ++q) {
        int gm = m0 + am[q];
        pa[q] = (gm < M) ? *reinterpret_cast<const float4*>(&A[(size_t)gm * lda + ak[q]]) : z4;
        int gn = n0 + bn[q];
        pb[q] = (gn < N) ? *reinterpret_cast<const float4*>(&B[(size_t)bk_[q] * ldb + gn]) : z4;
    }
#pragma unroll
    for (int q = 0; q < 2; ++q) {
        As[0][ak[q] + 0][am[q]] = pa[q].x; As[0][ak[q] + 1][am[q]] = pa[q].y;
        As[0][ak[q] + 2][am[q]] = pa[q].z; As[0][ak[q] + 3][am[q]] = pa[q].w;
        *reinterpret_cast<float4*>(&Bs[0][bk_[q]][bn[q]]) = pb[q];
    }
    __syncthreads();

    const int nk = K / BK;
    for (int t = 0; t < nk; ++t) {
        const int buf = t & 1;
        if (t + 1 < nk) {
            const int k0 = (t + 1) * BK;
#pragma unroll
            for (int q = 0; q < 2; ++q) {
                int gm = m0 + am[q];
                pa[q] = (gm < M) ? *reinterpret_cast<const float4*>(&A[(size_t)gm * lda + k0 + ak[q]]) : z4;
                int gn = n0 + bn[q];
                pb[q] = (gn < N) ? *reinterpret_cast<const float4*>(&B[(size_t)(k0 + bk_[q]) * ldb + gn]) : z4;
            }
        }
#pragma unroll
        for (int kk = 0; kk < BK; ++kk) {
            float4 av = *reinterpret_cast<const float4*>(&As[buf][kk][4 * tr]);
            const u64* bp = reinterpret_cast<const u64*>(&Bs[buf][kk][8 * tc]);
            u64 b0 = bp[0], b1 = bp[1], b2 = bp[2], b3 = bp[3];
            u64 a0 = pack2s(av.x), a1 = pack2s(av.y), a2 = pack2s(av.z), a3 = pack2s(av.w);
            fma2(acc[0][0], a0, b0); fma2(acc[0][1], a0, b1); fma2(acc[0][2], a0, b2); fma2(acc[0][3], a0, b3);
            fma2(acc[1][0], a1, b0); fma2(acc[1][1], a1, b1); fma2(acc[1][2], a1, b2); fma2(acc[1][3], a1, b3);
            fma2(acc[2][0], a2, b0); fma2(acc[2][1], a2, b1); fma2(acc[2][2], a2, b2); fma2(acc[2][3], a2, b3);
            fma2(acc[3][0], a3, b0); fma2(acc[3][1], a3, b1); fma2(acc[3][2], a3, b2); fma2(acc[3][3], a3, b3);
        }
        if (t + 1 < nk) {
            const int nb = buf ^ 1;
#pragma unroll
            for (int q = 0; q < 2; ++q) {
                As[nb][ak[q] + 0][am[q]] = pa[q].x; As[nb][ak[q] + 1][am[q]] = pa[q].y;
                As[nb][ak[q] + 2][am[q]] = pa[q].z; As[nb][ak[q] + 3][am[q]] = pa[q].w;
                *reinterpret_cast<float4*>(&Bs[nb][bk_[q]][bn[q]]) = pb[q];
            }
            __syncthreads();
        }
    }
#pragma unroll
    for (int r = 0; r < 4; ++r)
#pragma unroll
    for (int c = 0; c < 4; ++c) {
        int row = m0 + 4 * tr + r, col = n0 + 8 * tc + 2 * c;
        if (row < M && col < N)
            *reinterpret_cast<u64*>(&C[(size_t)row * ldc + col]) = acc[r][c];
    }
}

// ---------------- small helper kernels ----------------
__global__ void kzero(float* p, int n) {
    int i = blockIdx.x * blockDim.x + threadIdx.x;
    if (i < n) p[i] = 0.f;
}
__global__ void kcopy(float* dst, int ldd, const float* src, int lds, int rows, int cols) {
    int i = blockIdx.x * blockDim.x + threadIdx.x;
    if (i >= rows * cols) return;
    int r = i / cols, c = i - r * cols;
    dst[(size_t)r * ldd + c] = src[(size_t)r * lds + c];
}
__global__ void kaddb(float* dst, int ldd, const float* src, int lds, int rows, int cols) {
    int i = blockIdx.x * blockDim.x + threadIdx.x;
    if (i >= rows * cols) return;
    int r = i / cols, c = i - r * cols;
    dst[(size_t)r * ldd + c] += src[(size_t)r * lds + c];
}
__global__ void kvadd2(float* dst, const float* a, const float* b, int n) {
    int i = blockIdx.x * blockDim.x + threadIdx.x;
    if (i < n) dst[i] = a[i] + b[i];
}
__global__ void kvaddrow(float* dst, const float* src, int n) {
    int i = blockIdx.x * blockDim.x + threadIdx.x;
    if (i < n) dst[i] += src[i];
}
__global__ void kdiag(float* M) {   // acc->acc identity + homogeneous 1
    int i = threadIdx.x;
    if (i < PP) M[(size_t)(1536 + i) * ZP + 1536 + i] += 1.f;
    if (i == PP) M[(size_t)HOM * ZP + HOM] += 1.f;
}
__global__ void kp0(float* P) {     // P_0 = I[:,acc block]
    int i = blockIdx.x * blockDim.x + threadIdx.x;
    if (i >= ZP * PP) return;
    int r = i / PP, p = i - r * PP;
    P[(size_t)r * PW + p] = (r == 1536 + p) ? 1.f : 0.f;
}
__global__ void kqrev(float* Q, const float* V) {   // Q block i = V block 31-i
    int i = blockIdx.x * blockDim.x + threadIdx.x;
    if (i >= XCW * ZP) return;
    int row = i / ZP, col = i - row * ZP;
    int blk = row >> 6, f = row & 63;
    Q[(size_t)row * ZP + col] = V[(size_t)((31 - blk) * 64 + f) * ZP + col];
}
__global__ void khbuild(float* H, const float* Rs) {
    int i = blockIdx.x * blockDim.x + threadIdx.x;
    if (i >= XCW * ACW) return;
    int row = i / ACW, colx = i - row * ACW;
    int ib = row >> 6, f = row & 63;
    int jb = colx >> 5, p = colx & 31;
    int d = jb - ib;
    H[(size_t)row * ACW + colx] = (d >= 0) ? Rs[(size_t)f * ACW + d * PP + p] : 0.f;
}
__global__ void kzinit(float* Z) {
    int i = blockIdx.x * blockDim.x + threadIdx.x;
    if (i >= BB * ZP) return;
    Z[i] = ((i % ZP) == HOM) ? 1.f : 0.f;
}
__global__ void kepi(float* out, const float* A, const float* Z, int c) {
    int i = blockIdx.x * blockDim.x + threadIdx.x;
    if (i >= BB * ACW) return;
    int b = i >> 10, jp = i & 1023;
    int jj = jp >> 5, p = jp & 31;
    float cur = A[(size_t)b * ACW + jp];
    float prv = jj ? A[(size_t)b * ACW + jp - PP] : Z[(size_t)b * ZP + 1536 + p];
    out[((size_t)b * TT + c * CH + jj) * PP + p] = cur - prv;
}

// ---------------- host ----------------
static void gemm(const float* A, int lda, const float* B, int ldb,
                 float* C, int ldc, int M, int N, int K, int acc)
{
    dim3 g((unsigned)((N + BN - 1) / BN), (unsigned)((M + BM - 1) / BM));
    gemm_k<<<g, 128>>>(A, lda, B, ldb, C, ldc, M, N, K, acc);
}
#define L1D(n) (((n) + 255) / 256), 256

extern "C" void kernel_launch(void* const* d_in, const int* in_sizes, int n_in,
                              void* d_out, int out_size)
{
    const float* x    = (const float*)d_in[0];
    const float* WA   = (const float*)d_in[1];
    const float* bA   = (const float*)d_in[2];
    const float* WB0  = (const float*)d_in[3];
    const float* bB0  = (const float*)d_in[4];
    const float* WBr  = (const float*)d_in[5];
    const float* bBr  = (const float*)d_in[6];
    const float* WC   = (const float*)d_in[7];
    const float* bC   = (const float*)d_in[8];
    const float* Wout = (const float*)d_in[9];
    const float* bout = (const float*)d_in[10];
    float* out = (float*)d_out;

    float *M_, *M2_, *M4_, *M8_, *M16_, *N_, *T1_, *T2_, *P_, *V_, *Q_, *Rs_, *H_, *A_, *Z0_, *Z1_;
    cudaGetSymbolAddress((void**)&M_,  gM);   cudaGetSymbolAddress((void**)&M2_, gM2);
    cudaGetSymbolAddress((void**)&M4_, gM4);  cudaGetSymbolAddress((void**)&M8_, gM8);
    cudaGetSymbolAddress((void**)&M16_,gM16); cudaGetSymbolAddress((void**)&N_,  gN);
    cudaGetSymbolAddress((void**)&T1_, gT1);  cudaGetSymbolAddress((void**)&T2_, gT2);
    cudaGetSymbolAddress((void**)&P_,  gP);   cudaGetSymbolAddress((void**)&V_,  gV);
    cudaGetSymbolAddress((void**)&Q_,  gQ);   cudaGetSymbolAddress((void**)&Rs_, gRs);
    cudaGetSymbolAddress((void**)&H_,  gH);   cudaGetSymbolAddress((void**)&A_,  gA);
    cudaGetSymbolAddress((void**)&Z0_, gZ0);  cudaGetSymbolAddress((void**)&Z1_, gZ1);

    const int W2 = UU * UU;   // 262144

    // ---- build M (step matrix) and N (input matrix), homogeneous coords ----
    kzero<<<L1D(ZP*ZP)>>>(M_, ZP*ZP);
    kzero<<<L1D(64*ZP)>>>(N_, 64*ZP);

    // column block h1' (cols 0:512)
    kcopy<<<L1D(UU*UU)>>>(M_,               ZP, WA,            UU, UU, UU);
    kcopy<<<L1D(PP*UU)>>>(M_ + 1536*ZP,     ZP, WB0 + 64*UU,   UU, PP, UU);
    kvadd2<<<L1D(UU)>>>(M_ + (size_t)HOM*ZP, bA, bB0, UU);
    kcopy<<<L1D(64*UU)>>>(N_,               ZP, WB0,           UU, 64, UU);

    // column block h2' (cols 512:1024) = [h1'-map @ WC1 + bC1] @ WBr1 + WA2 + biases
    gemm(M_, ZP, WC, UU, T1_, UU, ZP, UU, UU, 0);
    kvaddrow<<<L1D(UU)>>>(T1_ + (size_t)HOM*UU, bC, UU);
    gemm(T1_, UU, WBr, UU, M_ + 512, ZP, ZP, UU, UU, 0);
    kaddb<<<L1D(UU*UU)>>>(M_ + (size_t)512*ZP + 512, ZP, WA + W2, UU, UU, UU);
    kvaddrow<<<L1D(UU)>>>(M_ + (size_t)HOM*ZP + 512, bA + UU, UU);
    kvaddrow<<<L1D(UU)>>>(M_ + (size_t)HOM*ZP + 512, bBr, UU);
    gemm(N_, ZP, WC, UU, T2_, UU, 64, UU, UU, 0);
    gemm(T2_, UU, WBr, UU, N_ + 512, ZP, 64, UU, UU, 0);

    // column block h3' (cols 1024:1536)
    gemm(M_ + 512, ZP, WC + W2, UU, T1_, UU, ZP, UU, UU, 0);
    kvaddrow<<<L1D(UU)>>>(T1_ + (size_t)HOM*UU, bC + UU, UU);
    gemm(T1_, UU, WBr + W2, UU, M_ + 1024, ZP, ZP, UU, UU, 0);
    kaddb<<<L1D(UU*UU)>>>(M_ + (size_t)1024*ZP + 1024, ZP, WA + 2*W2, UU, UU, UU);
    kvaddrow<<<L1D(UU)>>>(M_ + (size_t)HOM*ZP + 1024, bA + 2*UU, UU);
    kvaddrow<<<L1D(UU)>>>(M_ + (size_t)HOM*ZP + 1024, bBr + UU, UU);
    gemm(N_ + 512, ZP, WC + W2, UU, T2_, UU, 64, UU, UU, 0);
    gemm(T2_, UU, WBr + W2, UU, N_ + 1024, ZP, 64, UU, UU, 0);

    // column block acc' (cols 1536:1568) = [h3'-map @ WC3 + bC3] @ Wout + bout + I_acc
    gemm(M_ + 1024, ZP, WC + 2*W2, UU, T1_, UU, ZP, UU, UU, 0);
    kvaddrow<<<L1D(UU)>>>(T1_ + (size_t)HOM*UU, bC + 2*UU, UU);
    gemm(T1_, UU, Wout, PP, M_ + 1536, ZP, ZP, PP, UU, 0);
    kvaddrow<<<L1D(PP)>>>(M_ + (size_t)HOM*ZP + 1536, bout, PP);
    kdiag<<<1, 64>>>(M_);
    gemm(N_ + 1024, ZP, WC + 2*W2, UU, T2_, UU, 64, UU, UU, 0);
    gemm(T2_, UU, Wout, PP, N_ + 1536, ZP, 64, PP, UU, 0);

    // ---- powers of M ----
    gemm(M_,  ZP, M_,  ZP, M2_,  ZP, ZP, ZP, ZP, 0);
    gemm(M2_, ZP, M2_, ZP, M4_,  ZP, ZP, ZP, ZP, 0);
    gemm(M4_, ZP, M4_, ZP, M8_,  ZP, ZP, ZP, ZP, 0);
    gemm(M8_, ZP, M8_, ZP, M16_, ZP, ZP, ZP, ZP, 0);

    // ---- Pstack: P_d = M^d[:, acc], d = 0..32 (log-doubling) ----
    kp0<<<L1D(ZP*PP)>>>(P_);
    kcopy<<<L1D(ZP*PP)>>>(P_ + PP, PW, M_ + 1536, ZP, ZP, PP);
    gemm(M2_,  ZP, P_, PW, P_ + 2*PP,  PW, ZP, 2*PP,  ZP, 0);
    gemm(M4_,  ZP, P_, PW, P_ + 4*PP,  PW, ZP, 4*PP,  ZP, 0);
    gemm(M8_,  ZP, P_, PW, P_ + 8*PP,  PW, ZP, 8*PP,  ZP, 0);
    gemm(M16_, ZP, P_, PW, P_ + 16*PP, PW, ZP, 16*PP, ZP, 0);
    gemm(M16_, ZP, P_ + 16*PP, PW, P_ + 32*PP, PW, ZP, PP, ZP, 0);

    // ---- V_d = N M^d, d = 0..31 (log-doubling); Q = reversed V ----
    kcopy<<<L1D(64*ZP)>>>(V_, ZP, N_, ZP, 64, ZP);
    gemm(V_, ZP, M_,   ZP, V_ + (size_t)64*ZP,   ZP, 64,   ZP, ZP, 0);
    gemm(V_, ZP, M2_,  ZP, V_ + (size_t)128*ZP,  ZP, 128,  ZP, ZP, 0);
    gemm(V_, ZP, M4_,  ZP, V_ + (size_t)256*ZP,  ZP, 256,  ZP, ZP, 0);
    gemm(V_, ZP, M8_,  ZP, V_ + (size_t)512*ZP,  ZP, 512,  ZP, ZP, 0);
    gemm(V_, ZP, M16_, ZP, V_ + (size_t)1024*ZP, ZP, 1024, ZP, ZP, 0);
    kqrev<<<L1D(XCW*ZP)>>>(Q_, V_);

    // ---- R stack and causal-conv matrix H ----
    gemm(N_, ZP, P_, PW, Rs_, ACW, 64, ACW, ZP, 0);
    khbuild<<<L1D(XCW*ACW)>>>(H_, Rs_);

    // ---- main chunk loop ----
    kzinit<<<L1D(BB*ZP)>>>(Z0_);
    float* Z = Z0_;
    float* Zn = Z1_;
    for (int c = 0; c < NCH; ++c) {
        const float* Xc = x + (size_t)c * XCW;          // [BB, XCW], lda = TT*FF
        gemm(Z, ZP, P_ + PP, PW, A_, ACW, BB, ACW, ZP, 0);
        gemm(Xc, TT*FF, H_, ACW, A_, ACW, BB, ACW, XCW, 1);
        gemm(Z, ZP, M16_, ZP, Zn, ZP, BB, ZP, ZP, 0);
        gemm(Xc, TT*FF, Q_, ZP, Zn, ZP, BB, ZP, XCW, 1);
        kepi<<<L1D(BB*ACW)>>>(out, A_, Z, c);
        float* tmp = Z; Z = Zn; Zn = tmp;
    }
}

// round 9
// speedup vs baseline: 5.9657x; 1.6751x over previous
#include <cuda_runtime.h>
#include <cstdint>
#include <cstddef>

// Problem constants
#define BB 512
#define TT 512
#define FF 64
#define PP 32
#define UU 512

// Affine-state formulation
#define ZP   1600          // padded state dim [h1|h2|h3|acc|1|pad]
#define HOM  1568          // homogeneous-one index
#define CH   32            // chunk length
#define NCH  (TT/CH)       // 16 chunks
#define XCW  (CH*FF)       // 2048 : x K-width per chunk
#define YW   (CH*PP)       // 1024 : y columns per chunk
#define MROW (BB*NCH)      // 8192 : batched (b,c) rows

typedef unsigned long long u64;

// ---------------- device scratch (static, no allocs) ----------------
__device__ float gM[ZP*ZP], gM2[ZP*ZP], gM4[ZP*ZP], gM8[ZP*ZP], gM16[ZP*ZP], gM32[ZP*ZP];
__device__ float gN[64*ZP];
__device__ float gT1[ZP*UU];
__device__ float gT2[64*UU];
__device__ float gY[ZP*YW];          // Ystack: block j = M^j * D
__device__ float gV[XCW*ZP];         // V_d = N*M^d, d=0..31 (row blocks of 64)
__device__ float gQ[XCW*ZP];         // reversed V
__device__ float gNY[64*YW];         // N * Ystack
__device__ float gHy[XCW*YW];        // causal y-conv matrix
__device__ float gZX[MROW*ZP];       // per-chunk z partials / chain states
__device__ float gZ0[BB*ZP];

// ---------------- packed f32x2 helpers ----------------
__device__ __forceinline__ void fma2(u64& d, u64 a, u64 b) {
    asm("fma.rn.f32x2 %0, %1, %2, %0;" : "+l"(d) : "l"(a), "l"(b));
}
__device__ __forceinline__ u64 pack2(float x, float y) {
    u64 r;
    asm("mov.b64 %0, {%1, %2};" : "=l"(r)
        : "r"(__float_as_uint(x)), "r"(__float_as_uint(y)));
    return r;
}
__device__ __forceinline__ u64 pack2s(float x) {
    u64 r;
    asm("mov.b64 %0, {%1, %1};" : "=l"(r) : "r"(__float_as_uint(x)));
    return r;
}

// ---------------- generic fp32 GEMM: C = A*B (+C if accum) ----------------
// Row-major, runtime leading dims. M,N edge-guarded; K multiple of 16; N mult of 4.
#define BM 64
#define BN 64
#define BK 16

__global__ void __launch_bounds__(256) gemm_k(
    const float* __restrict__ A, int lda,
    const float* __restrict__ B, int ldb,
    float* __restrict__ C, int ldc,
    int M, int N, int K, int accum)
{
    __shared__ float As[2][BK][BM + 4];
    __shared__ float Bs[2][BK][BN];
    const int tid = threadIdx.x;
    const int m0 = blockIdx.y * BM, n0 = blockIdx.x * BN;
    const int tr = tid >> 4, tc = tid & 15;

    const int am = tid >> 2, ak = (tid & 3) * 4;   // A staging coords
    const int bk = tid >> 4, bn = (tid & 15) * 4;  // B staging coords
    const int gm = m0 + am;
    const int gn = n0 + bn;
    const bool aok = gm < M;
    const bool bok = gn < N;
    const float4 z4 = make_float4(0.f, 0.f, 0.f, 0.f);

    u64 acc[4][2];
#pragma unroll
    for (int r = 0; r < 4; ++r) { acc[r][0] = 0ull; acc[r][1] = 0ull; }
    if (accum) {
#pragma unroll
        for (int r = 0; r < 4; ++r) {
            int row = m0 + 4 * tr + r, col = n0 + 4 * tc;
            if (row < M && col < N) {
                ulonglong2 v = *reinterpret_cast<const ulonglong2*>(&C[(size_t)row * ldc + col]);
                acc[r][0] = v.x; acc[r][1] = v.y;
            }
        }
    }

    float4 pa = aok ? *reinterpret_cast<const float4*>(&A[(size_t)gm * lda + ak]) : z4;
    float4 pb = bok ? *reinterpret_cast<const float4*>(&B[(size_t)bk * ldb + gn]) : z4;
    As[0][ak + 0][am] = pa.x; As[0][ak + 1][am] = pa.y;
    As[0][ak + 2][am] = pa.z; As[0][ak + 3][am] = pa.w;
    *reinterpret_cast<float4*>(&Bs[0][bk][bn]) = pb;
    __syncthreads();

    const int nk = K / BK;
    for (int t = 0; t < nk; ++t) {
        const int buf = t & 1;
        if (t + 1 < nk) {
            const int k0 = (t + 1) * BK;
            pa = aok ? *reinterpret_cast<const float4*>(&A[(size_t)gm * lda + k0 + ak]) : z4;
            pb = bok ? *reinterpret_cast<const float4*>(&B[(size_t)(k0 + bk) * ldb + gn]) : z4;
        }
#pragma unroll
        for (int kk = 0; kk < BK; ++kk) {
            float4 av = *reinterpret_cast<const float4*>(&As[buf][kk][4 * tr]);
            const u64* bp = reinterpret_cast<const u64*>(&Bs[buf][kk][4 * tc]);
            u64 b0 = bp[0], b1 = bp[1];
            u64 a0 = pack2s(av.x), a1 = pack2s(av.y), a2 = pack2s(av.z), a3 = pack2s(av.w);
            fma2(acc[0][0], a0, b0); fma2(acc[0][1], a0, b1);
            fma2(acc[1][0], a1, b0); fma2(acc[1][1], a1, b1);
            fma2(acc[2][0], a2, b0); fma2(acc[2][1], a2, b1);
            fma2(acc[3][0], a3, b0); fma2(acc[3][1], a3, b1);
        }
        if (t + 1 < nk) {
            const int nb = buf ^ 1;
            As[nb][ak + 0][am] = pa.x; As[nb][ak + 1][am] = pa.y;
            As[nb][ak + 2][am] = pa.z; As[nb][ak + 3][am] = pa.w;
            *reinterpret_cast<float4*>(&Bs[nb][bk][bn]) = pb;
            __syncthreads();
        }
    }
#pragma unroll
    for (int r = 0; r < 4; ++r) {
        int row = m0 + 4 * tr + r, col = n0 + 4 * tc;
        if (row < M && col < N) {
            ulonglong2 v; v.x = acc[r][0]; v.y = acc[r][1];
            *reinterpret_cast<ulonglong2*>(&C[(size_t)row * ldc + col]) = v;
        }
    }
}

// ---------------- small helper kernels ----------------
__global__ void kzero(float* p, int n) {
    int i = blockIdx.x * blockDim.x + threadIdx.x;
    if (i < n) p[i] = 0.f;
}
__global__ void kcopy(float* dst, int ldd, const float* src, int lds, int rows, int cols) {
    int i = blockIdx.x * blockDim.x + threadIdx.x;
    if (i >= rows * cols) return;
    int r = i / cols, c = i - r * cols;
    dst[(size_t)r * ldd + c] = src[(size_t)r * lds + c];
}
__global__ void kaddb(float* dst, int ldd, const float* src, int lds, int rows, int cols) {
    int i = blockIdx.x * blockDim.x + threadIdx.x;
    if (i >= rows * cols) return;
    int r = i / cols, c = i - r * cols;
    dst[(size_t)r * ldd + c] += src[(size_t)r * lds + c];
}
__global__ void kvadd2(float* dst, const float* a, const float* b, int n) {
    int i = blockIdx.x * blockDim.x + threadIdx.x;
    if (i < n) dst[i] = a[i] + b[i];
}
__global__ void kvaddrow(float* dst, const float* src, int n) {
    int i = blockIdx.x * blockDim.x + threadIdx.x;
    if (i < n) dst[i] += src[i];
}
__global__ void kdiag(float* M) {   // acc->acc identity + homogeneous 1
    int i = threadIdx.x;
    if (i < PP) M[(size_t)(1536 + i) * ZP + 1536 + i] += 1.f;
    if (i == PP) M[(size_t)HOM * ZP + HOM] += 1.f;
}
// Hy[i*64+f, j*32+p] = (j==i) ? N[f,1536+p] : (j>i) ? NY[f, (j-i-1)*32+p] : 0
__global__ void khbuild_y(float* Hy, const float* NY, const float* Nm) {
    int idx = blockIdx.x * blockDim.x + threadIdx.x;
    if (idx >= XCW * YW) return;
    int row = idx >> 10, col = idx & 1023;
    int i = row >> 6, f = row & 63;
    int j = col >> 5, p = col & 31;
    float v = 0.f;
    if (j == i)      v = Nm[(size_t)f * ZP + 1536 + p];
    else if (j > i)  v = NY[(size_t)f * YW + (j - i - 1) * PP + p];
    Hy[idx] = v;
}
__global__ void kqrev(float* Q, const float* V) {   // Q block i = V block 31-i
    int idx = blockIdx.x * blockDim.x + threadIdx.x;
    if (idx >= XCW * ZP) return;
    int row = idx / ZP, col = idx - row * ZP;
    int i = row >> 6, f = row & 63;
    Q[(size_t)row * ZP + col] = V[(size_t)((31 - i) * 64 + f) * ZP + col];
}
__global__ void kzinit(float* Z) {
    int i = blockIdx.x * blockDim.x + threadIdx.x;
    if (i >= BB * ZP) return;
    Z[i] = ((i % ZP) == HOM) ? 1.f : 0.f;
}

// ---------------- host ----------------
static void gemm(const float* A, int lda, const float* B, int ldb,
                 float* C, int ldc, int M, int N, int K, int acc)
{
    dim3 g((unsigned)((N + BN - 1) / BN), (unsigned)((M + BM - 1) / BM));
    gemm_k<<<g, 256>>>(A, lda, B, ldb, C, ldc, M, N, K, acc);
}
#define L1D(n) (((n) + 255) / 256), 256

extern "C" void kernel_launch(void* const* d_in, const int* in_sizes, int n_in,
                              void* d_out, int out_size)
{
    const float* x    = (const float*)d_in[0];
    const float* WA   = (const float*)d_in[1];
    const float* bA   = (const float*)d_in[2];
    const float* WB0  = (const float*)d_in[3];
    const float* bB0  = (const float*)d_in[4];
    const float* WBr  = (const float*)d_in[5];
    const float* bBr  = (const float*)d_in[6];
    const float* WC   = (const float*)d_in[7];
    const float* bC   = (const float*)d_in[8];
    const float* Wout = (const float*)d_in[9];
    const float* bout = (const float*)d_in[10];
    float* out = (float*)d_out;

    float *M_, *M2_, *M4_, *M8_, *M16_, *M32_, *N_, *T1_, *T2_, *Y_, *V_, *Q_, *NY_, *Hy_, *ZX_, *Z0_;
    cudaGetSymbolAddress((void**)&M_,   gM);   cudaGetSymbolAddress((void**)&M2_, gM2);
    cudaGetSymbolAddress((void**)&M4_,  gM4);  cudaGetSymbolAddress((void**)&M8_, gM8);
    cudaGetSymbolAddress((void**)&M16_, gM16); cudaGetSymbolAddress((void**)&M32_,gM32);
    cudaGetSymbolAddress((void**)&N_,   gN);   cudaGetSymbolAddress((void**)&T1_, gT1);
    cudaGetSymbolAddress((void**)&T2_,  gT2);  cudaGetSymbolAddress((void**)&Y_,  gY);
    cudaGetSymbolAddress((void**)&V_,   gV);   cudaGetSymbolAddress((void**)&Q_,  gQ);
    cudaGetSymbolAddress((void**)&NY_,  gNY);  cudaGetSymbolAddress((void**)&Hy_, gHy);
    cudaGetSymbolAddress((void**)&ZX_,  gZX);  cudaGetSymbolAddress((void**)&Z0_, gZ0);

    const int W2 = UU * UU;

    // ---- build M (step matrix) and N (input matrix), homogeneous coords ----
    kzero<<<L1D(ZP*ZP)>>>(M_, ZP*ZP);
    kzero<<<L1D(64*ZP)>>>(N_, 64*ZP);

    // column block h1' (cols 0:512)
    kcopy<<<L1D(UU*UU)>>>(M_,           ZP, WA,          UU, UU, UU);
    kcopy<<<L1D(PP*UU)>>>(M_ + (size_t)1536*ZP, ZP, WB0 + 64*UU, UU, PP, UU);
    kvadd2<<<L1D(UU)>>>(M_ + (size_t)HOM*ZP, bA, bB0, UU);
    kcopy<<<L1D(64*UU)>>>(N_,           ZP, WB0,         UU, 64, UU);

    // column block h2' (cols 512:1024)
    gemm(M_, ZP, WC, UU, T1_, UU, ZP, UU, UU, 0);
    kvaddrow<<<L1D(UU)>>>(T1_ + (size_t)HOM*UU, bC, UU);
    gemm(T1_, UU, WBr, UU, M_ + 512, ZP, ZP, UU, UU, 0);
    kaddb<<<L1D(UU*UU)>>>(M_ + (size_t)512*ZP + 512, ZP, WA + W2, UU, UU, UU);
    kvaddrow<<<L1D(UU)>>>(M_ + (size_t)HOM*ZP + 512, bA + UU, UU);
    kvaddrow<<<L1D(UU)>>>(M_ + (size_t)HOM*ZP + 512, bBr, UU);
    gemm(N_, ZP, WC, UU, T2_, UU, 64, UU, UU, 0);
    gemm(T2_, UU, WBr, UU, N_ + 512, ZP, 64, UU, UU, 0);

    // column block h3' (cols 1024:1536)
    gemm(M_ + 512, ZP, WC + W2, UU, T1_, UU, ZP, UU, UU, 0);
    kvaddrow<<<L1D(UU)>>>(T1_ + (size_t)HOM*UU, bC + UU, UU);
    gemm(T1_, UU, WBr + W2, UU, M_ + 1024, ZP, ZP, UU, UU, 0);
    kaddb<<<L1D(UU*UU)>>>(M_ + (size_t)1024*ZP + 1024, ZP, WA + 2*W2, UU, UU, UU);
    kvaddrow<<<L1D(UU)>>>(M_ + (size_t)HOM*ZP + 1024, bA + 2*UU, UU);
    kvaddrow<<<L1D(UU)>>>(M_ + (size_t)HOM*ZP + 1024, bBr + UU, UU);
    gemm(N_ + 512, ZP, WC + W2, UU, T2_, UU, 64, UU, UU, 0);
    gemm(T2_, UU, WBr + W2, UU, N_ + 1024, ZP, 64, UU, UU, 0);

    // column block acc' (cols 1536:1568): readout D, then +I
    gemm(M_ + 1024, ZP, WC + 2*W2, UU, T1_, UU, ZP, UU, UU, 0);
    kvaddrow<<<L1D(UU)>>>(T1_ + (size_t)HOM*UU, bC + 2*UU, UU);
    gemm(T1_, UU, Wout, PP, M_ + 1536, ZP, ZP, PP, UU, 0);
    kvaddrow<<<L1D(PP)>>>(M_ + (size_t)HOM*ZP + 1536, bout, PP);
    // D = current acc-column block (pre-identity) -> seed of Ystack
    kcopy<<<L1D(ZP*PP)>>>(Y_, YW, M_ + 1536, ZP, ZP, PP);
    kdiag<<<1, 64>>>(M_);
    gemm(N_ + 1024, ZP, WC + 2*W2, UU, T2_, UU, 64, UU, UU, 0);
    gemm(T2_, UU, Wout, PP, N_ + 1536, ZP, 64, PP, UU, 0);

    // ---- powers of M ----
    gemm(M_,   ZP, M_,   ZP, M2_,  ZP, ZP, ZP, ZP, 0);
    gemm(M2_,  ZP, M2_,  ZP, M4_,  ZP, ZP, ZP, ZP, 0);
    gemm(M4_,  ZP, M4_,  ZP, M8_,  ZP, ZP, ZP, ZP, 0);
    gemm(M8_,  ZP, M8_,  ZP, M16_, ZP, ZP, ZP, ZP, 0);
    gemm(M16_, ZP, M16_, ZP, M32_, ZP, ZP, ZP, ZP, 0);

    // ---- Ystack: block j = M^j * D, j=0..31 (log-doubling) ----
    gemm(M_,   ZP, Y_, YW, Y_ + 32,  YW, ZP, 32,  ZP, 0);
    gemm(M2_,  ZP, Y_, YW, Y_ + 64,  YW, ZP, 64,  ZP, 0);
    gemm(M4_,  ZP, Y_, YW, Y_ + 128, YW, ZP, 128, ZP, 0);
    gemm(M8_,  ZP, Y_, YW, Y_ + 256, YW, ZP, 256, ZP, 0);
    gemm(M16_, ZP, Y_, YW, Y_ + 512, YW, ZP, 512, ZP, 0);

    // ---- V_d = N*M^d, d=0..31 (log-doubling); Q = reversed V ----
    kcopy<<<L1D(64*ZP)>>>(V_, ZP, N_, ZP, 64, ZP);
    gemm(V_, ZP, M_,   ZP, V_ + (size_t)64*ZP,   ZP, 64,   ZP, ZP, 0);
    gemm(V_, ZP, M2_,  ZP, V_ + (size_t)128*ZP,  ZP, 128,  ZP, ZP, 0);
    gemm(V_, ZP, M4_,  ZP, V_ + (size_t)256*ZP,  ZP, 256,  ZP, ZP, 0);
    gemm(V_, ZP, M8_,  ZP, V_ + (size_t)512*ZP,  ZP, 512,  ZP, ZP, 0);
    gemm(V_, ZP, M16_, ZP, V_ + (size_t)1024*ZP, ZP, 1024, ZP, ZP, 0);
    kqrev<<<L1D(XCW*ZP)>>>(Q_, V_);

    // ---- NY = N * Ystack ; Hy causal-conv matrix ----
    gemm(N_, ZP, Y_, YW, NY_, YW, 64, YW, ZP, 0);
    khbuild_y<<<L1D(XCW*YW)>>>(Hy_, NY_, N_);

    // ---- batched x-driven GEMMs (full chip) ----
    // x as [8192, 2048]: row (b*16+c) -> x + b*32768 + c*2048  (contiguous)
    // out as [8192, 1024]: row (b*16+c) -> out + b*16384 + c*1024
    gemm(x, XCW, Hy_, YW, out, YW, MROW, YW,  XCW, 0);
    gemm(x, XCW, Q_,  ZP, ZX_, ZP, MROW, ZP,  XCW, 0);

    // ---- serial z-chain: 16 chunks ----
    kzinit<<<L1D(BB*ZP)>>>(Z0_);
    for (int c = 0; c < NCH; ++c) {
        const float* zA = (c == 0) ? Z0_ : (ZX_ + (size_t)(c - 1) * ZP);
        int lza = (c == 0) ? ZP : (NCH * ZP);
        // y部分: out_chunk += z_c * Ystack
        gemm(zA, lza, Y_, YW, out + (size_t)c * YW, TT * PP, BB, YW, ZP, 1);
        // z_{c+1} = (X_c*Q precomputed) += z_c * M32
        gemm(zA, lza, M32_, ZP, ZX_ + (size_t)c * ZP, NCH * ZP, BB, ZP, ZP, 1);
    }
}

// round 11
// speedup vs baseline: 10.8343x; 1.8161x over previous
#include <cuda_runtime.h>
#include <cuda_bf16.h>
#include <cstdint>
#include <cstddef>

// Problem constants
#define BB 512
#define TT 512
#define FF 64
#define PP 32
#define UU 512

// Affine-state formulation
#define ZP   1600          // padded state dim [h1|h2|h3|acc|1|pad]
#define HOM  1568          // homogeneous-one index
#define CH   32            // chunk length
#define NCH  (TT/CH)       // 16 chunks
#define XCW  (CH*FF)       // 2048 : x K-width per chunk
#define YW   (CH*PP)       // 1024 : y columns per chunk
#define MROW (BB*NCH)      // 8192 : batched (b,c) rows
#define CW   (YW+ZP)       // 2624 : concatenated [y | z] width

typedef unsigned long long u64;

// ---------------- device scratch (static, no allocs) ----------------
__device__ __align__(256) float gM[ZP*ZP], gM2[ZP*ZP], gM4[ZP*ZP], gM8[ZP*ZP],
                                gM16[ZP*ZP], gM32[ZP*ZP];
__device__ __align__(256) float gN[64*ZP];
__device__ __align__(256) float gT1[ZP*UU];
__device__ __align__(256) float gT2[64*UU];
__device__ __align__(256) float gY[ZP*YW];
__device__ __align__(256) float gV[XCW*ZP];
__device__ __align__(256) float gNY[64*YW];
__device__ __align__(256) float gWcat[ZP*CW];          // [Ystack | M32]
__device__ __align__(256) float gHcat[(size_t)XCW*CW]; // [Hy | Q]
__device__ __align__(256) float gXC[(size_t)MROW*CW];  // [y | z] per (b,chunk)
__device__ __align__(256) float gZ0[BB*ZP];

// ================= split-bf16 mma.sync GEMM =================
// C = A*B (+C if accum). fp32 row-major, runtime ld*. K%32==0, N even.
#define TBM 128
#define TBN 128
#define TBK 32
#define ROWB 80                       // smem row pitch (64B data + 16B pad)
#define TILEB (128*ROWB)              // 10240 B per bf16 tile
#define BUFB (4*TILEB)                // Ahi,Alo,Bhi,Blo
#define GSMEM (2*BUFB)                // 81920 B double-buffered

__device__ __forceinline__ uint32_t bfpack(float x, float y) {  // lo=x, hi=y
    uint32_t r;
    asm("cvt.rn.bf16x2.f32 %0, %1, %2;" : "=r"(r) : "f"(y), "f"(x));
    return r;
}
__device__ __forceinline__ void ldsm4(uint32_t& r0, uint32_t& r1,
                                      uint32_t& r2, uint32_t& r3, uint32_t a) {
    asm volatile("ldmatrix.sync.aligned.m8n8.x4.shared.b16 {%0,%1,%2,%3}, [%4];"
                 : "=r"(r0), "=r"(r1), "=r"(r2), "=r"(r3) : "r"(a));
}
__device__ __forceinline__ void mma16816(float* c, const uint32_t* a, const uint32_t* b) {
    asm volatile("mma.sync.aligned.m16n8k16.row.col.f32.bf16.bf16.f32 "
                 "{%0,%1,%2,%3}, {%4,%5,%6,%7}, {%8,%9}, {%0,%1,%2,%3};"
                 : "+f"(c[0]), "+f"(c[1]), "+f"(c[2]), "+f"(c[3])
                 : "r"(a[0]), "r"(a[1]), "r"(a[2]), "r"(a[3]),
                   "r"(b[0]), "r"(b[1]));
}

__device__ __forceinline__ void ldg_tiles(
    const float* __restrict__ A, int lda, int M, int m0,
    const float* __restrict__ B, int ldb, int N, int n0,
    int k0, int smr, int kh, float4 ra[4], float rb[16])
{
    const float4 z4 = make_float4(0.f, 0.f, 0.f, 0.f);
    if (m0 + smr < M) {
        const float* ap = A + (size_t)(m0 + smr) * lda + k0 + kh;
#pragma unroll
        for (int j = 0; j < 4; ++j)
            ra[j] = *reinterpret_cast<const float4*>(ap + 4 * j);
    } else {
#pragma unroll
        for (int j = 0; j < 4; ++j) ra[j] = z4;
    }
    if (n0 + smr < N) {
        const float* bp = B + (size_t)(k0 + kh) * ldb + (n0 + smr);
#pragma unroll
        for (int j = 0; j < 16; ++j) rb[j] = bp[(size_t)j * ldb];
    } else {
#pragma unroll
        for (int j = 0; j < 16; ++j) rb[j] = 0.f;
    }
}

__device__ __forceinline__ void split8(const float* v, uint32_t* hw, uint32_t* lw) {
#pragma unroll
    for (int j = 0; j < 8; ++j) {
        float x = v[2 * j], y = v[2 * j + 1];
        float hx = __bfloat162float(__float2bfloat16(x));
        float hy = __bfloat162float(__float2bfloat16(y));
        hw[j] = bfpack(x, y);
        lw[j] = bfpack(x - hx, y - hy);
    }
}

__device__ __forceinline__ void sts_tiles(char* smem, int buf, int smr, int kh,
                                          const float4 ra[4], const float rb[16])
{
    char* base = smem + buf * BUFB;
    uint32_t hw[8], lw[8];
    float av[16];
#pragma unroll
    for (int j = 0; j < 4; ++j) {
        av[4*j] = ra[j].x; av[4*j+1] = ra[j].y; av[4*j+2] = ra[j].z; av[4*j+3] = ra[j].w;
    }
    split8(av, hw, lw);
    {
        char* d = base + smr * ROWB + kh * 2;
        *reinterpret_cast<uint4*>(d)      = make_uint4(hw[0], hw[1], hw[2], hw[3]);
        *reinterpret_cast<uint4*>(d + 16) = make_uint4(hw[4], hw[5], hw[6], hw[7]);
        char* d2 = d + TILEB;
        *reinterpret_cast<uint4*>(d2)      = make_uint4(lw[0], lw[1], lw[2], lw[3]);
        *reinterpret_cast<uint4*>(d2 + 16) = make_uint4(lw[4], lw[5], lw[6], lw[7]);
    }
    split8(rb, hw, lw);
    {
        char* d = base + 2 * TILEB + smr * ROWB + kh * 2;
        *reinterpret_cast<uint4*>(d)      = make_uint4(hw[0], hw[1], hw[2], hw[3]);
        *reinterpret_cast<uint4*>(d + 16) = make_uint4(hw[4], hw[5], hw[6], hw[7]);
        char* d2 = d + TILEB;
        *reinterpret_cast<uint4*>(d2)      = make_uint4(lw[0], lw[1], lw[2], lw[3]);
        *reinterpret_cast<uint4*>(d2 + 16) = make_uint4(lw[4], lw[5], lw[6], lw[7]);
    }
}

__global__ void __launch_bounds__(256, 1) tcgemm_k(
    const float* __restrict__ A, int lda,
    const float* __restrict__ B, int ldb,
    float* __restrict__ C, int ldc,
    int M, int N, int K, int accum)
{
    extern __shared__ __align__(16) char smem[];
    const uint32_t sb = (uint32_t)__cvta_generic_to_shared(smem);
    const int tid  = threadIdx.x;
    const int wid  = tid >> 5;
    const int lane = tid & 31;
    const int m0 = blockIdx.y * TBM;
    const int n0 = blockIdx.x * TBN;
    const int wm = (wid >> 2) * 64;        // warp M offset
    const int wn = (wid & 3) * 32;         // warp N offset
    const int smr = tid >> 1;              // staging row (A:m, B:n)
    const int kh  = (tid & 1) * 16;        // staging k offset

    float acc[4][4][4];
#pragma unroll
    for (int mi = 0; mi < 4; ++mi)
#pragma unroll
        for (int ni = 0; ni < 4; ++ni)
#pragma unroll
            for (int r = 0; r < 4; ++r) acc[mi][ni][r] = 0.f;

    // precomputed ldmatrix lane offsets
    const uint32_t a_lrow = (uint32_t)(lane & 15);
    const uint32_t a_lchk = (uint32_t)(lane >> 4);
    const uint32_t b_lrow = (uint32_t)(((lane >> 4) << 3) + (lane & 7));
    const uint32_t b_lchk = (uint32_t)((lane >> 3) & 1);

    const int nk = K / TBK;
    float4 ra[4]; float rb[16];
    ldg_tiles(A, lda, M, m0, B, ldb, N, n0, 0, smr, kh, ra, rb);
    sts_tiles(smem, 0, smr, kh, ra, rb);
    __syncthreads();

    for (int s = 0; s < nk; ++s) {
        if (s + 1 < nk)
            ldg_tiles(A, lda, M, m0, B, ldb, N, n0, (s + 1) * TBK, smr, kh, ra, rb);

        const uint32_t base = sb + (uint32_t)((s & 1) * BUFB);
#pragma unroll
        for (int kk = 0; kk < 2; ++kk) {
            uint32_t ah[4][4], al[4][4], bh[4][2], bl[4][2];
#pragma unroll
            for (int mi = 0; mi < 4; ++mi) {
                uint32_t off = (uint32_t)(wm + mi * 16 + a_lrow) * ROWB
                             + (uint32_t)(kk * 2 + a_lchk) * 16;
                ldsm4(ah[mi][0], ah[mi][1], ah[mi][2], ah[mi][3], base + off);
                ldsm4(al[mi][0], al[mi][1], al[mi][2], al[mi][3], base + TILEB + off);
            }
#pragma unroll
            for (int h = 0; h < 2; ++h) {
                uint32_t off = (uint32_t)(wn + h * 16 + b_lrow) * ROWB
                             + (uint32_t)(kk * 2 + b_lchk) * 16;
                uint32_t t0, t1, t2, t3;
                ldsm4(t0, t1, t2, t3, base + 2 * TILEB + off);
                bh[2*h][0] = t0; bh[2*h][1] = t1; bh[2*h+1][0] = t2; bh[2*h+1][1] = t3;
                ldsm4(t0, t1, t2, t3, base + 3 * TILEB + off);
                bl[2*h][0] = t0; bl[2*h][1] = t1; bl[2*h+1][0] = t2; bl[2*h+1][1] = t3;
            }
#pragma unroll
            for (int mi = 0; mi < 4; ++mi)
#pragma unroll
                for (int ni = 0; ni < 4; ++ni) {
                    mma16816(acc[mi][ni], ah[mi], bh[ni]);
                    mma16816(acc[mi][ni], ah[mi], bl[ni]);
                    mma16816(acc[mi][ni], al[mi], bh[ni]);
                }
        }
        __syncthreads();
        if (s + 1 < nk) {
            sts_tiles(smem, (s + 1) & 1, smr, kh, ra, rb);
            __syncthreads();
        }
    }

    // epilogue
#pragma unroll
    for (int mi = 0; mi < 4; ++mi) {
        int r0 = m0 + wm + mi * 16 + (lane >> 2);
        int r1 = r0 + 8;
#pragma unroll
        for (int ni = 0; ni < 4; ++ni) {
            int cc = n0 + wn + ni * 8 + (lane & 3) * 2;
            if (cc < N) {
                if (r0 < M) {
                    float2* p = reinterpret_cast<float2*>(&C[(size_t)r0 * ldc + cc]);
                    float2 v = accum ? *p : make_float2(0.f, 0.f);
                    v.x += acc[mi][ni][0]; v.y += acc[mi][ni][1];
                    *p = v;
                }
                if (r1 < M) {
                    float2* p = reinterpret_cast<float2*>(&C[(size_t)r1 * ldc + cc]);
                    float2 v = accum ? *p : make_float2(0.f, 0.f);
                    v.x += acc[mi][ni][2]; v.y += acc[mi][ni][3];
                    *p = v;
                }
            }
        }
    }
}

// ---------------- small helper kernels ----------------
__global__ void kzero(float* p, int n) {
    int i = blockIdx.x * blockDim.x + threadIdx.x;
    if (i < n) p[i] = 0.f;
}
__global__ void kcopy(float* dst, int ldd, const float* src, int lds, int rows, int cols) {
    int i = blockIdx.x * blockDim.x + threadIdx.x;
    if (i >= rows * cols) return;
    int r = i / cols, c = i - r * cols;
    dst[(size_t)r * ldd + c] = src[(size_t)r * lds + c];
}
__global__ void kaddb(float* dst, int ldd, const float* src, int lds, int rows, int cols) {
    int i = blockIdx.x * blockDim.x + threadIdx.x;
    if (i >= rows * cols) return;
    int r = i / cols, c = i - r * cols;
    dst[(size_t)r * ldd + c] += src[(size_t)r * lds + c];
}
__global__ void kvadd2(float* dst, const float* a, const float* b, int n) {
    int i = blockIdx.x * blockDim.x + threadIdx.x;
    if (i < n) dst[i] = a[i] + b[i];
}
__global__ void kvaddrow(float* dst, const float* src, int n) {
    int i = blockIdx.x * blockDim.x + threadIdx.x;
    if (i < n) dst[i] += src[i];
}
__global__ void kdiag(float* M) {
    int i = threadIdx.x;
    if (i < PP) M[(size_t)(1536 + i) * ZP + 1536 + i] += 1.f;
    if (i == PP) M[(size_t)HOM * ZP + HOM] += 1.f;
}
__global__ void khbuild_y(float* Hcat, const float* NY, const float* Nm) {
    int idx = blockIdx.x * blockDim.x + threadIdx.x;
    if (idx >= XCW * YW) return;
    int row = idx >> 10, col = idx & 1023;
    int i = row >> 6, f = row & 63;
    int j = col >> 5, p = col & 31;
    float v = 0.f;
    if (j == i)      v = Nm[(size_t)f * ZP + 1536 + p];
    else if (j > i)  v = NY[(size_t)f * YW + (j - i - 1) * PP + p];
    Hcat[(size_t)row * CW + col] = v;
}
__global__ void kqrev(float* Hcat, const float* V) {
    int idx = blockIdx.x * blockDim.x + threadIdx.x;
    if (idx >= XCW * ZP) return;
    int row = idx / ZP, col = idx - row * ZP;
    int i = row >> 6, f = row & 63;
    Hcat[(size_t)row * CW + YW + col] = V[(size_t)((31 - i) * 64 + f) * ZP + col];
}
__global__ void kzinit(float* Z) {
    int i = blockIdx.x * blockDim.x + threadIdx.x;
    if (i >= BB * ZP) return;
    Z[i] = ((i % ZP) == HOM) ? 1.f : 0.f;
}
__global__ void kout(float* out, const float* XC) {
    int i = blockIdx.x * blockDim.x + threadIdx.x;
    if (i >= BB * TT * PP) return;
    int b = i / (TT * PP), r = i - b * (TT * PP);
    int t = r >> 5, p = r & 31;
    int c = t >> 5, j = t & 31;
    out[i] = XC[((size_t)b * NCH + c) * CW + j * PP + p];
}

// ---------------- host ----------------
static void gemm(const float* A, int lda, const float* B, int ldb,
                 float* C, int ldc, int M, int N, int K, int acc)
{
    dim3 g((unsigned)((N + TBN - 1) / TBN), (unsigned)((M + TBM - 1) / TBM));
    tcgemm_k<<<g, 256, GSMEM>>>(A, lda, B, ldb, C, ldc, M, N, K, acc);
}
#define L1D(n) (((n) + 255) / 256), 256

extern "C" void kernel_launch(void* const* d_in, const int* in_sizes, int n_in,
                              void* d_out, int out_size)
{
    const float* x    = (const float*)d_in[0];
    const float* WA   = (const float*)d_in[1];
    const float* bA   = (const float*)d_in[2];
    const float* WB0  = (const float*)d_in[3];
    const float* bB0  = (const float*)d_in[4];
    const float* WBr  = (const float*)d_in[5];
    const float* bBr  = (const float*)d_in[6];
    const float* WC   = (const float*)d_in[7];
    const float* bC   = (const float*)d_in[8];
    const float* Wout = (const float*)d_in[9];
    const float* bout = (const float*)d_in[10];
    float* out = (float*)d_out;

    static int attr_done = 0;
    if (!attr_done) {
        cudaFuncSetAttribute(tcgemm_k, cudaFuncAttributeMaxDynamicSharedMemorySize, GSMEM);
        attr_done = 1;
    }

    float *M_, *M2_, *M4_, *M8_, *M16_, *M32_, *N_, *T1_, *T2_, *Y_, *V_, *NY_;
    float *Wcat_, *Hcat_, *XC_, *Z0_;
    cudaGetSymbolAddress((void**)&M_,   gM);    cudaGetSymbolAddress((void**)&M2_,  gM2);
    cudaGetSymbolAddress((void**)&M4_,  gM4);   cudaGetSymbolAddress((void**)&M8_,  gM8);
    cudaGetSymbolAddress((void**)&M16_, gM16);  cudaGetSymbolAddress((void**)&M32_, gM32);
    cudaGetSymbolAddress((void**)&N_,   gN);    cudaGetSymbolAddress((void**)&T1_,  gT1);
    cudaGetSymbolAddress((void**)&T2_,  gT2);   cudaGetSymbolAddress((void**)&Y_,   gY);
    cudaGetSymbolAddress((void**)&V_,   gV);    cudaGetSymbolAddress((void**)&NY_,  gNY);
    cudaGetSymbolAddress((void**)&Wcat_, gWcat); cudaGetSymbolAddress((void**)&Hcat_, gHcat);
    cudaGetSymbolAddress((void**)&XC_,  gXC);   cudaGetSymbolAddress((void**)&Z0_,  gZ0);

    const int W2 = UU * UU;

    // ---- build M (step matrix) and N (input matrix) ----
    kzero<<<L1D(ZP*ZP)>>>(M_, ZP*ZP);
    kzero<<<L1D(64*ZP)>>>(N_, 64*ZP);

    kcopy<<<L1D(UU*UU)>>>(M_,                   ZP, WA,          UU, UU, UU);
    kcopy<<<L1D(PP*UU)>>>(M_ + (size_t)1536*ZP, ZP, WB0 + 64*UU, UU, PP, UU);
    kvadd2<<<L1D(UU)>>>(M_ + (size_t)HOM*ZP, bA, bB0, UU);
    kcopy<<<L1D(64*UU)>>>(N_,                   ZP, WB0,         UU, 64, UU);

    gemm(M_, ZP, WC, UU, T1_, UU, ZP, UU, UU, 0);
    kvaddrow<<<L1D(UU)>>>(T1_ + (size_t)HOM*UU, bC, UU);
    gemm(T1_, UU, WBr, UU, M_ + 512, ZP, ZP, UU, UU, 0);
    kaddb<<<L1D(UU*UU)>>>(M_ + (size_t)512*ZP + 512, ZP, WA + W2, UU, UU, UU);
    kvaddrow<<<L1D(UU)>>>(M_ + (size_t)HOM*ZP + 512, bA + UU, UU);
    kvaddrow<<<L1D(UU)>>>(M_ + (size_t)HOM*ZP + 512, bBr, UU);
    gemm(N_, ZP, WC, UU, T2_, UU, 64, UU, UU, 0);
    gemm(T2_, UU, WBr, UU, N_ + 512, ZP, 64, UU, UU, 0);

    gemm(M_ + 512, ZP, WC + W2, UU, T1_, UU, ZP, UU, UU, 0);
    kvaddrow<<<L1D(UU)>>>(T1_ + (size_t)HOM*UU, bC + UU, UU);
    gemm(T1_, UU, WBr + W2, UU, M_ + 1024, ZP, ZP, UU, UU, 0);
    kaddb<<<L1D(UU*UU)>>>(M_ + (size_t)1024*ZP + 1024, ZP, WA + 2*W2, UU, UU, UU);
    kvaddrow<<<L1D(UU)>>>(M_ + (size_t)HOM*ZP + 1024, bA + 2*UU, UU);
    kvaddrow<<<L1D(UU)>>>(M_ + (size_t)HOM*ZP + 1024, bBr + UU, UU);
    gemm(N_ + 512, ZP, WC + W2, UU, T2_, UU, 64, UU, UU, 0);
    gemm(T2_, UU, WBr + W2, UU, N_ + 1024, ZP, 64, UU, UU, 0);

    gemm(M_ + 1024, ZP, WC + 2*W2, UU, T1_, UU, ZP, UU, UU, 0);
    kvaddrow<<<L1D(UU)>>>(T1_ + (size_t)HOM*UU, bC + 2*UU, UU);
    gemm(T1_, UU, Wout, PP, M_ + 1536, ZP, ZP, PP, UU, 0);
    kvaddrow<<<L1D(PP)>>>(M_ + (size_t)HOM*ZP + 1536, bout, PP);
    kcopy<<<L1D(ZP*PP)>>>(Y_, YW, M_ + 1536, ZP, ZP, PP);   // D seed (pre-identity)
    kdiag<<<1, 64>>>(M_);
    gemm(N_ + 1024, ZP, WC + 2*W2, UU, T2_, UU, 64, UU, UU, 0);
    gemm(T2_, UU, Wout, PP, N_ + 1536, ZP, 64, PP, UU, 0);

    // ---- powers of M ----
    gemm(M_,   ZP, M_,   ZP, M2_,  ZP, ZP, ZP, ZP, 0);
    gemm(M2_,  ZP, M2_,  ZP, M4_,  ZP, ZP, ZP, ZP, 0);
    gemm(M4_,  ZP, M4_,  ZP, M8_,  ZP, ZP, ZP, ZP, 0);
    gemm(M8_,  ZP, M8_,  ZP, M16_, ZP, ZP, ZP, ZP, 0);
    gemm(M16_, ZP, M16_, ZP, M32_, ZP, ZP, ZP, ZP, 0);

    // ---- Ystack: block j = M^j * D (log-doubling) ----
    gemm(M_,   ZP, Y_, YW, Y_ + 32,  YW, ZP, 32,  ZP, 0);
    gemm(M2_,  ZP, Y_, YW, Y_ + 64,  YW, ZP, 64,  ZP, 0);
    gemm(M4_,  ZP, Y_, YW, Y_ + 128, YW, ZP, 128, ZP, 0);
    gemm(M8_,  ZP, Y_, YW, Y_ + 256, YW, ZP, 256, ZP, 0);
    gemm(M16_, ZP, Y_, YW, Y_ + 512, YW, ZP, 512, ZP, 0);

    // ---- V_d = N*M^d (log-doubling) ----
    kcopy<<<L1D(64*ZP)>>>(V_, ZP, N_, ZP, 64, ZP);
    gemm(V_, ZP, M_,   ZP, V_ + (size_t)64*ZP,   ZP, 64,   ZP, ZP, 0);
    gemm(V_, ZP, M2_,  ZP, V_ + (size_t)128*ZP,  ZP, 128,  ZP, ZP, 0);
    gemm(V_, ZP, M4_,  ZP, V_ + (size_t)256*ZP,  ZP, 256,  ZP, ZP, 0);
    gemm(V_, ZP, M8_,  ZP, V_ + (size_t)512*ZP,  ZP, 512,  ZP, ZP, 0);
    gemm(V_, ZP, M16_, ZP, V_ + (size_t)1024*ZP, ZP, 1024, ZP, ZP, 0);

    // ---- Hcat = [Hy | Q], Wcat = [Ystack | M32] ----
    gemm(N_, ZP, Y_, YW, NY_, YW, 64, YW, ZP, 0);
    khbuild_y<<<L1D(XCW*YW)>>>(Hcat_, NY_, N_);
    kqrev<<<L1D(XCW*ZP)>>>(Hcat_, V_);
    kcopy<<<L1D(ZP*YW)>>>(Wcat_,      CW, Y_,   YW, ZP, YW);
    kcopy<<<L1D(ZP*ZP)>>>(Wcat_ + YW, CW, M32_, ZP, ZP, ZP);

    // ---- one giant x-driven GEMM: XC = X * Hcat (8192 x 2624 x 2048) ----
    gemm(x, XCW, Hcat_, CW, XC_, CW, MROW, CW, XCW, 0);

    // ---- serial z-chain: XC[c] += z_c * Wcat ----
    kzinit<<<L1D(BB*ZP)>>>(Z0_);
    for (int c = 0; c < NCH; ++c) {
        const float* zA = (c == 0) ? Z0_ : (XC_ + (size_t)(c - 1) * CW + YW);
        int lza = (c == 0) ? ZP : (NCH * CW);
        gemm(zA, lza, Wcat_, CW, XC_ + (size_t)c * CW, NCH * CW, BB, CW, ZP, 1);
    }

    // ---- scatter y-part to output ----
    kout<<<L1D(BB*TT*PP)>>>(out, XC_);
}

// round 12
// speedup vs baseline: 12.3410x; 1.1391x over previous
#include <cuda_runtime.h>
#include <cuda_bf16.h>
#include <cstdint>
#include <cstddef>

// Problem constants
#define BB 512
#define TT 512
#define FF 64
#define PP 32
#define UU 512

// Affine-state formulation
#define ZP   1600
#define HOM  1568
#define CH   32
#define NCH  (TT/CH)
#define XCW  (CH*FF)       // 2048
#define YW   (CH*PP)       // 1024
#define MROW (BB*NCH)      // 8192
#define CW   (YW+ZP)       // 2624

typedef unsigned long long u64;
typedef __nv_bfloat16 bf16;

// ---------------- fp32 scratch ----------------
__device__ __align__(256) float gM[ZP*ZP], gM2[ZP*ZP], gM4[ZP*ZP], gM8[ZP*ZP],
                                gM16[ZP*ZP], gM32[ZP*ZP];
__device__ __align__(256) float gN[64*ZP];
__device__ __align__(256) float gT1[ZP*UU];
__device__ __align__(256) float gT2[64*UU];
__device__ __align__(256) float gY[ZP*YW];
__device__ __align__(256) float gV[(size_t)XCW*ZP];
__device__ __align__(256) float gNY[64*YW];
__device__ __align__(256) float gWcat[(size_t)ZP*CW];
__device__ __align__(256) float gHcat[(size_t)XCW*CW];
__device__ __align__(256) float gXC[(size_t)MROW*CW];
__device__ __align__(256) float gZ0[BB*ZP];

// ---------------- bf16 split planes ----------------
__device__ __align__(256) bf16 gm1h[ZP*ZP],  gm1l[ZP*ZP];
__device__ __align__(256) bf16 gm2h[ZP*ZP],  gm2l[ZP*ZP];
__device__ __align__(256) bf16 gm4h[ZP*ZP],  gm4l[ZP*ZP];
__device__ __align__(256) bf16 gm8h[ZP*ZP],  gm8l[ZP*ZP];
__device__ __align__(256) bf16 gm16h[ZP*ZP], gm16l[ZP*ZP];
__device__ __align__(256) bf16 gybh[ZP*512], gybl[ZP*512];
__device__ __align__(256) bf16 gvbh[(size_t)1024*ZP], gvbl[(size_t)1024*ZP];
__device__ __align__(256) bf16 ghh[(size_t)XCW*CW], ghl[(size_t)XCW*CW];
__device__ __align__(256) bf16 gwh[(size_t)ZP*CW],  gwl[(size_t)ZP*CW];
__device__ __align__(256) bf16 gxh[(size_t)MROW*XCW], gxl[(size_t)MROW*XCW];
__device__ __align__(256) bf16 gzh[BB*ZP], gzl[BB*ZP];

// ================= shared PTX helpers =================
__device__ __forceinline__ uint32_t bfpack(float x, float y) {  // lo=x, hi=y
    uint32_t r;
    asm("cvt.rn.bf16x2.f32 %0, %1, %2;" : "=r"(r) : "f"(y), "f"(x));
    return r;
}
__device__ __forceinline__ void ldsm4(uint32_t& r0, uint32_t& r1,
                                      uint32_t& r2, uint32_t& r3, uint32_t a) {
    asm volatile("ldmatrix.sync.aligned.m8n8.x4.shared.b16 {%0,%1,%2,%3}, [%4];"
                 : "=r"(r0), "=r"(r1), "=r"(r2), "=r"(r3) : "r"(a));
}
__device__ __forceinline__ void ldsm4t(uint32_t& r0, uint32_t& r1,
                                       uint32_t& r2, uint32_t& r3, uint32_t a) {
    asm volatile("ldmatrix.sync.aligned.m8n8.x4.trans.shared.b16 {%0,%1,%2,%3}, [%4];"
                 : "=r"(r0), "=r"(r1), "=r"(r2), "=r"(r3) : "r"(a));
}
__device__ __forceinline__ void mma16816(float* c, const uint32_t* a, const uint32_t* b) {
    asm volatile("mma.sync.aligned.m16n8k16.row.col.f32.bf16.bf16.f32 "
                 "{%0,%1,%2,%3}, {%4,%5,%6,%7}, {%8,%9}, {%0,%1,%2,%3};"
                 : "+f"(c[0]), "+f"(c[1]), "+f"(c[2]), "+f"(c[3])
                 : "r"(a[0]), "r"(a[1]), "r"(a[2]), "r"(a[3]),
                   "r"(b[0]), "r"(b[1]));
}
__device__ __forceinline__ void cpa16(uint32_t d, const void* g, int bytes) {
    asm volatile("cp.async.cg.shared.global [%0], [%1], 16, %2;"
                 :: "r"(d), "l"(g), "r"(bytes));
}
__device__ __forceinline__ void cpcommit() { asm volatile("cp.async.commit_group;"); }
template<int n> __device__ __forceinline__ void cpwait() {
    asm volatile("cp.async.wait_group %0;" :: "n"(n));
}

// ================= fast path: pre-split bf16 GEMM =================
// C(fp32, ldc) = Ahi/Alo(M x K, pitch lda) * Bhi/Blo(K x N, pitch ldb) (+C)
// 3-term split product. K % 32 == 0; M,N % 8 == 0 (edge-guarded to tiles).
#define S2   4
#define AROW 80                 // 64B data + 16 pad
#define BROW 272                // 256B data + 16 pad
#define A_T  (128*AROW)         // 10240 (one plane)
#define B_T  (32*BROW)          // 8704
#define SLOT (2*A_T + 2*B_T)    // 37888
#define GS2  (S2*SLOT)          // 151552

__device__ __forceinline__ void issue_stage(
    uint32_t sb, int s, int m0, int n0, int M, int N, int lda, int ldb,
    const bf16* __restrict__ Ah, const bf16* __restrict__ Al,
    const bf16* __restrict__ Bh, const bf16* __restrict__ Bl, int tid)
{
    const int k0 = s * 32;
    const uint32_t sl = sb + (uint32_t)((s % S2) * SLOT);
#pragma unroll
    for (int q = 0; q < 2; ++q) {
        int c = tid + q * 256;
        int m = c >> 2, kc = c & 3;
        int row = m0 + m;
        int bytes = (row < M) ? 16 : 0;
        int rs = bytes ? row : 0;
        const bf16* s1 = Ah + (size_t)rs * lda + k0 + kc * 8;
        const bf16* s2 = Al + (size_t)rs * lda + k0 + kc * 8;
        cpa16(sl + m * AROW + kc * 16, s1, bytes);
        cpa16(sl + A_T + m * AROW + kc * 16, s2, bytes);
    }
#pragma unroll
    for (int q = 0; q < 2; ++q) {
        int c = tid + q * 256;
        int k = c >> 4, nc = c & 15;
        int col = n0 + nc * 8;
        int bytes = (col < N) ? 16 : 0;
        int cs = bytes ? col : 0;
        const bf16* s1 = Bh + (size_t)(k0 + k) * ldb + cs;
        const bf16* s2 = Bl + (size_t)(k0 + k) * ldb + cs;
        cpa16(sl + 2 * A_T + k * BROW + nc * 16, s1, bytes);
        cpa16(sl + 2 * A_T + B_T + k * BROW + nc * 16, s2, bytes);
    }
    cpcommit();
}

__global__ void __launch_bounds__(256, 1) gemm_bf(
    const bf16* __restrict__ Ah, const bf16* __restrict__ Al, int lda,
    const bf16* __restrict__ Bh, const bf16* __restrict__ Bl, int ldb,
    float* __restrict__ C, int ldc, int M, int N, int K, int accum)
{
    extern __shared__ __align__(16) char smem[];
    const uint32_t sb = (uint32_t)__cvta_generic_to_shared(smem);
    const int tid  = threadIdx.x;
    const int wid  = tid >> 5;
    const int lane = tid & 31;
    const int m0 = blockIdx.y * 128;
    const int n0 = blockIdx.x * 128;
    const int wm = (wid >> 2) * 64;
    const int wn = (wid & 3) * 32;

    float acc[4][4][4];
#pragma unroll
    for (int mi = 0; mi < 4; ++mi)
#pragma unroll
        for (int ni = 0; ni < 4; ++ni)
#pragma unroll
            for (int r = 0; r < 4; ++r) acc[mi][ni][r] = 0.f;

    const int nk = K / 32;
    const int pro = (S2 - 1 < nk) ? S2 - 1 : nk;
    for (int s = 0; s < pro; ++s)
        issue_stage(sb, s, m0, n0, M, N, lda, ldb, Ah, Al, Bh, Bl, tid);

    const uint32_t a_lrow = (uint32_t)(lane & 15);
    const uint32_t a_lchk = (uint32_t)(lane >> 4);
    const uint32_t b_krow = (uint32_t)(lane & 15);
    const uint32_t b_ncol = (uint32_t)((lane >> 4) * 8);

    for (int s = 0; s < nk; ++s) {
        cpwait<S2 - 2>();
        __syncthreads();
        if (s + S2 - 1 < nk)
            issue_stage(sb, s + S2 - 1, m0, n0, M, N, lda, ldb, Ah, Al, Bh, Bl, tid);

        const uint32_t base = sb + (uint32_t)((s % S2) * SLOT);
#pragma unroll
        for (int kk = 0; kk < 2; ++kk) {
            uint32_t ah[4][4], al[4][4], bh[4][2], bl[4][2];
#pragma unroll
            for (int mi = 0; mi < 4; ++mi) {
                uint32_t off = (uint32_t)(wm + mi * 16 + a_lrow) * AROW
                             + (uint32_t)(kk * 2 + a_lchk) * 16;
                ldsm4(ah[mi][0], ah[mi][1], ah[mi][2], ah[mi][3], base + off);
                ldsm4(al[mi][0], al[mi][1], al[mi][2], al[mi][3], base + A_T + off);
            }
#pragma unroll
            for (int h = 0; h < 2; ++h) {
                uint32_t off = (uint32_t)(kk * 16 + b_krow) * BROW
                             + (uint32_t)(wn + h * 16 + b_ncol) * 2;
                uint32_t t0, t1, t2, t3;
                ldsm4t(t0, t1, t2, t3, base + 2 * A_T + off);
                bh[2*h][0] = t0; bh[2*h][1] = t1; bh[2*h+1][0] = t2; bh[2*h+1][1] = t3;
                ldsm4t(t0, t1, t2, t3, base + 2 * A_T + B_T + off);
                bl[2*h][0] = t0; bl[2*h][1] = t1; bl[2*h+1][0] = t2; bl[2*h+1][1] = t3;
            }
#pragma unroll
            for (int mi = 0; mi < 4; ++mi)
#pragma unroll
                for (int ni = 0; ni < 4; ++ni) {
                    mma16816(acc[mi][ni], ah[mi], bh[ni]);
                    mma16816(acc[mi][ni], ah[mi], bl[ni]);
                    mma16816(acc[mi][ni], al[mi], bh[ni]);
                }
        }
    }

    // epilogue
#pragma unroll
    for (int mi = 0; mi < 4; ++mi) {
        int r0 = m0 + wm + mi * 16 + (lane >> 2);
        int r1 = r0 + 8;
#pragma unroll
        for (int ni = 0; ni < 4; ++ni) {
            int cc = n0 + wn + ni * 8 + (lane & 3) * 2;
            if (cc < N) {
                if (r0 < M) {
                    float2* p = reinterpret_cast<float2*>(&C[(size_t)r0 * ldc + cc]);
                    float2 v = accum ? *p : make_float2(0.f, 0.f);
                    v.x += acc[mi][ni][0]; v.y += acc[mi][ni][1];
                    *p = v;
                }
                if (r1 < M) {
                    float2* p = reinterpret_cast<float2*>(&C[(size_t)r1 * ldc + cc]);
                    float2 v = accum ? *p : make_float2(0.f, 0.f);
                    v.x += acc[mi][ni][2]; v.y += acc[mi][ni][3];
                    *p = v;
                }
            }
        }
    }
}

// ================= slow path: fp32-input GEMM (round-11, for small builds) ==
#define TBM 128
#define TBN 128
#define TBK 32
#define ROWB 80
#define TILEB (128*ROWB)
#define BUFB (4*TILEB)
#define GSMEM (2*BUFB)

__device__ __forceinline__ void ldg_tiles(
    const float* __restrict__ A, int lda, int M, int m0,
    const float* __restrict__ B, int ldb, int N, int n0,
    int k0, int smr, int kh, float4 ra[4], float rb[16])
{
    const float4 z4 = make_float4(0.f, 0.f, 0.f, 0.f);
    if (m0 + smr < M) {
        const float* ap = A + (size_t)(m0 + smr) * lda + k0 + kh;
#pragma unroll
        for (int j = 0; j < 4; ++j)
            ra[j] = *reinterpret_cast<const float4*>(ap + 4 * j);
    } else {
#pragma unroll
        for (int j = 0; j < 4; ++j) ra[j] = z4;
    }
    if (n0 + smr < N) {
        const float* bp = B + (size_t)(k0 + kh) * ldb + (n0 + smr);
#pragma unroll
        for (int j = 0; j < 16; ++j) rb[j] = bp[(size_t)j * ldb];
    } else {
#pragma unroll
        for (int j = 0; j < 16; ++j) rb[j] = 0.f;
    }
}
__device__ __forceinline__ void split8(const float* v, uint32_t* hw, uint32_t* lw) {
#pragma unroll
    for (int j = 0; j < 8; ++j) {
        float x = v[2 * j], y = v[2 * j + 1];
        float hx = __bfloat162float(__float2bfloat16(x));
        float hy = __bfloat162float(__float2bfloat16(y));
        hw[j] = bfpack(x, y);
        lw[j] = bfpack(x - hx, y - hy);
    }
}
__device__ __forceinline__ void sts_tiles(char* smem, int buf, int smr, int kh,
                                          const float4 ra[4], const float rb[16])
{
    char* base = smem + buf * BUFB;
    uint32_t hw[8], lw[8];
    float av[16];
#pragma unroll
    for (int j = 0; j < 4; ++j) {
        av[4*j] = ra[j].x; av[4*j+1] = ra[j].y; av[4*j+2] = ra[j].z; av[4*j+3] = ra[j].w;
    }
    split8(av, hw, lw);
    {
        char* d = base + smr * ROWB + kh * 2;
        *reinterpret_cast<uint4*>(d)      = make_uint4(hw[0], hw[1], hw[2], hw[3]);
        *reinterpret_cast<uint4*>(d + 16) = make_uint4(hw[4], hw[5], hw[6], hw[7]);
        char* d2 = d + TILEB;
        *reinterpret_cast<uint4*>(d2)      = make_uint4(lw[0], lw[1], lw[2], lw[3]);
        *reinterpret_cast<uint4*>(d2 + 16) = make_uint4(lw[4], lw[5], lw[6], lw[7]);
    }
    split8(rb, hw, lw);
    {
        char* d = base + 2 * TILEB + smr * ROWB + kh * 2;
        *reinterpret_cast<uint4*>(d)      = make_uint4(hw[0], hw[1], hw[2], hw[3]);
        *reinterpret_cast<uint4*>(d + 16) = make_uint4(hw[4], hw[5], hw[6], hw[7]);
        char* d2 = d + TILEB;
        *reinterpret_cast<uint4*>(d2)      = make_uint4(lw[0], lw[1], lw[2], lw[3]);
        *reinterpret_cast<uint4*>(d2 + 16) = make_uint4(lw[4], lw[5], lw[6], lw[7]);
    }
}

__global__ void __launch_bounds__(256, 1) tcgemm_k(
    const float* __restrict__ A, int lda,
    const float* __restrict__ B, int ldb,
    float* __restrict__ C, int ldc,
    int M, int N, int K, int accum)
{
    extern __shared__ __align__(16) char smem[];
    const uint32_t sb = (uint32_t)__cvta_generic_to_shared(smem);
    const int tid  = threadIdx.x;
    const int wid  = tid >> 5;
    const int lane = tid & 31;
    const int m0 = blockIdx.y * TBM;
    const int n0 = blockIdx.x * TBN;
    const int wm = (wid >> 2) * 64;
    const int wn = (wid & 3) * 32;
    const int smr = tid >> 1;
    const int kh  = (tid & 1) * 16;

    float acc[4][4][4];
#pragma unroll
    for (int mi = 0; mi < 4; ++mi)
#pragma unroll
        for (int ni = 0; ni < 4; ++ni)
#pragma unroll
            for (int r = 0; r < 4; ++r) acc[mi][ni][r] = 0.f;

    const uint32_t a_lrow = (uint32_t)(lane & 15);
    const uint32_t a_lchk = (uint32_t)(lane >> 4);
    const uint32_t b_lrow = (uint32_t)(((lane >> 4) << 3) + (lane & 7));
    const uint32_t b_lchk = (uint32_t)((lane >> 3) & 1);

    const int nk = K / TBK;
    float4 ra[4]; float rb[16];
    ldg_tiles(A, lda, M, m0, B, ldb, N, n0, 0, smr, kh, ra, rb);
    sts_tiles(smem, 0, smr, kh, ra, rb);
    __syncthreads();

    for (int s = 0; s < nk; ++s) {
        if (s + 1 < nk)
            ldg_tiles(A, lda, M, m0, B, ldb, N, n0, (s + 1) * TBK, smr, kh, ra, rb);
        const uint32_t base = sb + (uint32_t)((s & 1) * BUFB);
#pragma unroll
        for (int kk = 0; kk < 2; ++kk) {
            uint32_t ah[4][4], al[4][4], bh[4][2], bl[4][2];
#pragma unroll
            for (int mi = 0; mi < 4; ++mi) {
                uint32_t off = (uint32_t)(wm + mi * 16 + a_lrow) * ROWB
                             + (uint32_t)(kk * 2 + a_lchk) * 16;
                ldsm4(ah[mi][0], ah[mi][1], ah[mi][2], ah[mi][3], base + off);
                ldsm4(al[mi][0], al[mi][1], al[mi][2], al[mi][3], base + TILEB + off);
            }
#pragma unroll
            for (int h = 0; h < 2; ++h) {
                uint32_t off = (uint32_t)(wn + h * 16 + b_lrow) * ROWB
                             + (uint32_t)(kk * 2 + b_lchk) * 16;
                uint32_t t0, t1, t2, t3;
                ldsm4(t0, t1, t2, t3, base + 2 * TILEB + off);
                bh[2*h][0] = t0; bh[2*h][1] = t1; bh[2*h+1][0] = t2; bh[2*h+1][1] = t3;
                ldsm4(t0, t1, t2, t3, base + 3 * TILEB + off);
                bl[2*h][0] = t0; bl[2*h][1] = t1; bl[2*h+1][0] = t2; bl[2*h+1][1] = t3;
            }
#pragma unroll
            for (int mi = 0; mi < 4; ++mi)
#pragma unroll
                for (int ni = 0; ni < 4; ++ni) {
                    mma16816(acc[mi][ni], ah[mi], bh[ni]);
                    mma16816(acc[mi][ni], ah[mi], bl[ni]);
                    mma16816(acc[mi][ni], al[mi], bh[ni]);
                }
        }
        __syncthreads();
        if (s + 1 < nk) {
            sts_tiles(smem, (s + 1) & 1, smr, kh, ra, rb);
            __syncthreads();
        }
    }
#pragma unroll
    for (int mi = 0; mi < 4; ++mi) {
        int r0 = m0 + wm + mi * 16 + (lane >> 2);
        int r1 = r0 + 8;
#pragma unroll
        for (int ni = 0; ni < 4; ++ni) {
            int cc = n0 + wn + ni * 8 + (lane & 3) * 2;
            if (cc < N) {
                if (r0 < M) {
                    float2* p = reinterpret_cast<float2*>(&C[(size_t)r0 * ldc + cc]);
                    float2 v = accum ? *p : make_float2(0.f, 0.f);
                    v.x += acc[mi][ni][0]; v.y += acc[mi][ni][1];
                    *p = v;
                }
                if (r1 < M) {
                    float2* p = reinterpret_cast<float2*>(&C[(size_t)r1 * ldc + cc]);
                    float2 v = accum ? *p : make_float2(0.f, 0.f);
                    v.x += acc[mi][ni][2]; v.y += acc[mi][ni][3];
                    *p = v;
                }
            }
        }
    }
}

// ---------------- small helper kernels ----------------
__global__ void kzero(float* p, int n) {
    int i = blockIdx.x * blockDim.x + threadIdx.x;
    if (i < n) p[i] = 0.f;
}
__global__ void kcopy(float* dst, int ldd, const float* src, int lds, int rows, int cols) {
    int i = blockIdx.x * blockDim.x + threadIdx.x;
    if (i >= rows * cols) return;
    int r = i / cols, c = i - r * cols;
    dst[(size_t)r * ldd + c] = src[(size_t)r * lds + c];
}
__global__ void kaddb(float* dst, int ldd, const float* src, int lds, int rows, int cols) {
    int i = blockIdx.x * blockDim.x + threadIdx.x;
    if (i >= rows * cols) return;
    int r = i / cols, c = i - r * cols;
    dst[(size_t)r * ldd + c] += src[(size_t)r * lds + c];
}
__global__ void kvadd2(float* dst, const float* a, const float* b, int n) {
    int i = blockIdx.x * blockDim.x + threadIdx.x;
    if (i < n) dst[i] = a[i] + b[i];
}
__global__ void kvaddrow(float* dst, const float* src, int n) {
    int i = blockIdx.x * blockDim.x + threadIdx.x;
    if (i < n) dst[i] += src[i];
}
__global__ void kdiag(float* M) {
    int i = threadIdx.x;
    if (i < PP) M[(size_t)(1536 + i) * ZP + 1536 + i] += 1.f;
    if (i == PP) M[(size_t)HOM * ZP + HOM] += 1.f;
}
__global__ void khbuild_y(float* Hcat, const float* NY, const float* Nm) {
    int idx = blockIdx.x * blockDim.x + threadIdx.x;
    if (idx >= XCW * YW) return;
    int row = idx >> 10, col = idx & 1023;
    int i = row >> 6, f = row & 63;
    int j = col >> 5, p = col & 31;
    float v = 0.f;
    if (j == i)      v = Nm[(size_t)f * ZP + 1536 + p];
    else if (j > i)  v = NY[(size_t)f * YW + (j - i - 1) * PP + p];
    Hcat[(size_t)row * CW + col] = v;
}
__global__ void kqrev(float* Hcat, const float* V) {
    int idx = blockIdx.x * blockDim.x + threadIdx.x;
    if (idx >= XCW * ZP) return;
    int row = idx / ZP, col = idx - row * ZP;
    int i = row >> 6, f = row & 63;
    Hcat[(size_t)row * CW + YW + col] = V[(size_t)((31 - i) * 64 + f) * ZP + col];
}
__global__ void kzinit(float* Z) {
    int i = blockIdx.x * blockDim.x + threadIdx.x;
    if (i >= BB * ZP) return;
    Z[i] = ((i % ZP) == HOM) ? 1.f : 0.f;
}
__global__ void kout(float* out, const float* XC) {
    int i = blockIdx.x * blockDim.x + threadIdx.x;
    if (i >= BB * TT * PP) return;
    int b = i / (TT * PP), r = i - b * (TT * PP);
    int t = r >> 5, p = r & 31;
    int c = t >> 5, j = t & 31;
    out[i] = XC[((size_t)b * NCH + c) * CW + j * PP + p];
}
// fp32 (strided) -> compact bf16 hi/lo planes
__global__ void ksplit(const float* __restrict__ src, int lds,
                       bf16* __restrict__ hi, bf16* __restrict__ lo,
                       int rows, int cols) {
    int i = blockIdx.x * blockDim.x + threadIdx.x;
    if (i >= rows * cols) return;
    int r = i / cols, c = i - r * cols;
    float v = src[(size_t)r * lds + c];
    bf16 h = __float2bfloat16(v);
    hi[(size_t)r * cols + c] = h;
    lo[(size_t)r * cols + c] = __float2bfloat16(v - __bfloat162float(h));
}

// ---------------- host ----------------
static void gemm(const float* A, int lda, const float* B, int ldb,
                 float* C, int ldc, int M, int N, int K, int acc)
{
    dim3 g((unsigned)((N + TBN - 1) / TBN), (unsigned)((M + TBM - 1) / TBM));
    tcgemm_k<<<g, 256, GSMEM>>>(A, lda, B, ldb, C, ldc, M, N, K, acc);
}
static void gemmF(const bf16* Ah, const bf16* Al, int lda,
                  const bf16* Bh, const bf16* Bl, int ldb,
                  float* C, int ldc, int M, int N, int K, int acc)
{
    dim3 g((unsigned)((N + 127) / 128), (unsigned)((M + 127) / 128));
    gemm_bf<<<g, 256, GS2>>>(Ah, Al, lda, Bh, Bl, ldb, C, ldc, M, N, K, acc);
}
#define L1D(n) (((n) + 255) / 256), 256
static void split(const float* src, int lds, bf16* hi, bf16* lo, int rows, int cols) {
    ksplit<<<L1D(rows * cols)>>>(src, lds, hi, lo, rows, cols);
}

extern "C" void kernel_launch(void* const* d_in, const int* in_sizes, int n_in,
                              void* d_out, int out_size)
{
    const float* x    = (const float*)d_in[0];
    const float* WA   = (const float*)d_in[1];
    const float* bA   = (const float*)d_in[2];
    const float* WB0  = (const float*)d_in[3];
    const float* bB0  = (const float*)d_in[4];
    const float* WBr  = (const float*)d_in[5];
    const float* bBr  = (const float*)d_in[6];
    const float* WC   = (const float*)d_in[7];
    const float* bC   = (const float*)d_in[8];
    const float* Wout = (const float*)d_in[9];
    const float* bout = (const float*)d_in[10];
    float* out = (float*)d_out;

    static int attr_done = 0;
    if (!attr_done) {
        cudaFuncSetAttribute(tcgemm_k, cudaFuncAttributeMaxDynamicSharedMemorySize, GSMEM);
        cudaFuncSetAttribute(gemm_bf,  cudaFuncAttributeMaxDynamicSharedMemorySize, GS2);
        attr_done = 1;
    }

    float *M_, *M2_, *M4_, *M8_, *M16_, *M32_, *N_, *T1_, *T2_, *Y_, *V_, *NY_;
    float *Wcat_, *Hcat_, *XC_, *Z0_;
    cudaGetSymbolAddress((void**)&M_,   gM);    cudaGetSymbolAddress((void**)&M2_,  gM2);
    cudaGetSymbolAddress((void**)&M4_,  gM4);   cudaGetSymbolAddress((void**)&M8_,  gM8);
    cudaGetSymbolAddress((void**)&M16_, gM16);  cudaGetSymbolAddress((void**)&M32_, gM32);
    cudaGetSymbolAddress((void**)&N_,   gN);    cudaGetSymbolAddress((void**)&T1_,  gT1);
    cudaGetSymbolAddress((void**)&T2_,  gT2);   cudaGetSymbolAddress((void**)&Y_,   gY);
    cudaGetSymbolAddress((void**)&V_,   gV);    cudaGetSymbolAddress((void**)&NY_,  gNY);
    cudaGetSymbolAddress((void**)&Wcat_, gWcat); cudaGetSymbolAddress((void**)&Hcat_, gHcat);
    cudaGetSymbolAddress((void**)&XC_,  gXC);   cudaGetSymbolAddress((void**)&Z0_,  gZ0);

    bf16 *m1h, *m1l, *m2h, *m2l, *m4h, *m4l, *m8h, *m8l, *m16h, *m16l;
    bf16 *ybh, *ybl, *vbh, *vbl, *hh, *hl, *wh, *wl, *xh, *xl, *zh, *zl;
    cudaGetSymbolAddress((void**)&m1h,  gm1h);  cudaGetSymbolAddress((void**)&m1l,  gm1l);
    cudaGetSymbolAddress((void**)&m2h,  gm2h);  cudaGetSymbolAddress((void**)&m2l,  gm2l);
    cudaGetSymbolAddress((void**)&m4h,  gm4h);  cudaGetSymbolAddress((void**)&m4l,  gm4l);
    cudaGetSymbolAddress((void**)&m8h,  gm8h);  cudaGetSymbolAddress((void**)&m8l,  gm8l);
    cudaGetSymbolAddress((void**)&m16h, gm16h); cudaGetSymbolAddress((void**)&m16l, gm16l);
    cudaGetSymbolAddress((void**)&ybh,  gybh);  cudaGetSymbolAddress((void**)&ybl,  gybl);
    cudaGetSymbolAddress((void**)&vbh,  gvbh);  cudaGetSymbolAddress((void**)&vbl,  gvbl);
    cudaGetSymbolAddress((void**)&hh,   ghh);   cudaGetSymbolAddress((void**)&hl,   ghl);
    cudaGetSymbolAddress((void**)&wh,   gwh);   cudaGetSymbolAddress((void**)&wl,   gwl);
    cudaGetSymbolAddress((void**)&xh,   gxh);   cudaGetSymbolAddress((void**)&xl,   gxl);
    cudaGetSymbolAddress((void**)&zh,   gzh);   cudaGetSymbolAddress((void**)&zl,   gzl);

    const int W2 = UU * UU;

    // ---- build M (step matrix) and N (input matrix) — slow path ----
    kzero<<<L1D(ZP*ZP)>>>(M_, ZP*ZP);
    kzero<<<L1D(64*ZP)>>>(N_, 64*ZP);

    kcopy<<<L1D(UU*UU)>>>(M_,                   ZP, WA,          UU, UU, UU);
    kcopy<<<L1D(PP*UU)>>>(M_ + (size_t)1536*ZP, ZP, WB0 + 64*UU, UU, PP, UU);
    kvadd2<<<L1D(UU)>>>(M_ + (size_t)HOM*ZP, bA, bB0, UU);
    kcopy<<<L1D(64*UU)>>>(N_,                   ZP, WB0,         UU, 64, UU);

    gemm(M_, ZP, WC, UU, T1_, UU, ZP, UU, UU, 0);
    kvaddrow<<<L1D(UU)>>>(T1_ + (size_t)HOM*UU, bC, UU);
    gemm(T1_, UU, WBr, UU, M_ + 512, ZP, ZP, UU, UU, 0);
    kaddb<<<L1D(UU*UU)>>>(M_ + (size_t)512*ZP + 512, ZP, WA + W2, UU, UU, UU);
    kvaddrow<<<L1D(UU)>>>(M_ + (size_t)HOM*ZP + 512, bA + UU, UU);
    kvaddrow<<<L1D(UU)>>>(M_ + (size_t)HOM*ZP + 512, bBr, UU);
    gemm(N_, ZP, WC, UU, T2_, UU, 64, UU, UU, 0);
    gemm(T2_, UU, WBr, UU, N_ + 512, ZP, 64, UU, UU, 0);

    gemm(M_ + 512, ZP, WC + W2, UU, T1_, UU, ZP, UU, UU, 0);
    kvaddrow<<<L1D(UU)>>>(T1_ + (size_t)HOM*UU, bC + UU, UU);
    gemm(T1_, UU, WBr + W2, UU, M_ + 1024, ZP, ZP, UU, UU, 0);
    kaddb<<<L1D(UU*UU)>>>(M_ + (size_t)1024*ZP + 1024, ZP, WA + 2*W2, UU, UU, UU);
    kvaddrow<<<L1D(UU)>>>(M_ + (size_t)HOM*ZP + 1024, bA + 2*UU, UU);
    kvaddrow<<<L1D(UU)>>>(M_ + (size_t)HOM*ZP + 1024, bBr + UU, UU);
    gemm(N_ + 512, ZP, WC + W2, UU, T2_, UU, 64, UU, UU, 0);
    gemm(T2_, UU, WBr + W2, UU, N_ + 1024, ZP, 64, UU, UU, 0);

    gemm(M_ + 1024, ZP, WC + 2*W2, UU, T1_, UU, ZP, UU, UU, 0);
    kvaddrow<<<L1D(UU)>>>(T1_ + (size_t)HOM*UU, bC + 2*UU, UU);
    gemm(T1_, UU, Wout, PP, M_ + 1536, ZP, ZP, PP, UU, 0);
    kvaddrow<<<L1D(PP)>>>(M_ + (size_t)HOM*ZP + 1536, bout, PP);
    kcopy<<<L1D(ZP*PP)>>>(Y_, YW, M_ + 1536, ZP, ZP, PP);   // D seed (pre-identity)
    kdiag<<<1, 64>>>(M_);
    gemm(N_ + 1024, ZP, WC + 2*W2, UU, T2_, UU, 64, UU, UU, 0);
    gemm(T2_, UU, Wout, PP, N_ + 1536, ZP, 64, PP, UU, 0);

    // ---- powers of M (fast path, split once each) ----
    split(M_, ZP, m1h, m1l, ZP, ZP);
    gemmF(m1h, m1l, ZP, m1h, m1l, ZP, M2_, ZP, ZP, ZP, ZP, 0);
    split(M2_, ZP, m2h, m2l, ZP, ZP);
    gemmF(m2h, m2l, ZP, m2h, m2l, ZP, M4_, ZP, ZP, ZP, ZP, 0);
    split(M4_, ZP, m4h, m4l, ZP, ZP);
    gemmF(m4h, m4l, ZP, m4h, m4l, ZP, M8_, ZP, ZP, ZP, ZP, 0);
    split(M8_, ZP, m8h, m8l, ZP, ZP);
    gemmF(m8h, m8l, ZP, m8h, m8l, ZP, M16_, ZP, ZP, ZP, ZP, 0);
    split(M16_, ZP, m16h, m16l, ZP, ZP);
    gemmF(m16h, m16l, ZP, m16h, m16l, ZP, M32_, ZP, ZP, ZP, ZP, 0);

    // ---- Ystack: Y[:, w:2w] = M^w * Y[:, 0:w] ----
    const bf16* mph[5] = {m1h, m2h, m4h, m8h, m16h};
    const bf16* mpl[5] = {m1l, m2l, m4l, m8l, m16l};
    for (int d = 0, w = 32; d < 5; ++d, w *= 2) {
        split(Y_, YW, ybh, ybl, ZP, w);
        gemmF(mph[d], mpl[d], ZP, ybh, ybl, w, Y_ + w, YW, ZP, w, ZP, 0);
    }

    // ---- V_d = N*M^d : V[r:2r] = V[0:r] * M^r ----
    kcopy<<<L1D(64*ZP)>>>(V_, ZP, N_, ZP, 64, ZP);
    for (int d = 0, r = 64; d < 5; ++d, r *= 2) {
        split(V_, ZP, vbh, vbl, r, ZP);
        gemmF(vbh, vbl, ZP, mph[d], mpl[d], ZP, V_ + (size_t)r * ZP, ZP, r, ZP, ZP, 0);
    }

    // ---- Hcat = [Hy | Q], Wcat = [Ystack | M32] ----
    gemm(N_, ZP, Y_, YW, NY_, YW, 64, YW, ZP, 0);
    khbuild_y<<<L1D(XCW*YW)>>>(Hcat_, NY_, N_);
    kqrev<<<L1D(XCW*ZP)>>>(Hcat_, V_);
    kcopy<<<L1D(ZP*YW)>>>(Wcat_,      CW, Y_,   YW, ZP, YW);
    kcopy<<<L1D(ZP*ZP)>>>(Wcat_ + YW, CW, M32_, ZP, ZP, ZP);
    split(Hcat_, CW, hh, hl, XCW, CW);
    split(Wcat_, CW, wh, wl, ZP, CW);
    split(x, XCW, xh, xl, MROW, XCW);

    // ---- one giant x-driven GEMM: XC = X * Hcat (8192 x 2624 x 2048) ----
    gemmF(xh, xl, XCW, hh, hl, CW, XC_, CW, MROW, CW, XCW, 0);

    // ---- serial z-chain: XC[c] += z_c * Wcat ----
    kzinit<<<L1D(BB*ZP)>>>(Z0_);
    for (int c = 0; c < NCH; ++c) {
        const float* zA = (c == 0) ? Z0_ : (XC_ + (size_t)(c - 1) * CW + YW);
        int lza = (c == 0) ? ZP : (NCH * CW);
        split(zA, lza, zh, zl, BB, ZP);
        gemmF(zh, zl, ZP, wh, wl, CW, XC_ + (size_t)c * CW, NCH * CW, BB, CW, ZP, 1);
    }

    // ---- scatter y-part to output ----
    kout<<<L1D(BB*TT*PP)>>>(out, XC_);
}

// round 13
// speedup vs baseline: 14.3791x; 1.1652x over previous
#include <cuda_runtime.h>
#include <cuda_bf16.h>
#include <cstdint>
#include <cstddef>

// Problem constants
#define BB 512
#define TT 512
#define FF 64
#define PP 32
#define UU 512

// Affine-state formulation
#define ZP   1600
#define HOM  1568
#define CH   32
#define NCH  (TT/CH)
#define XCW  (CH*FF)       // 2048
#define YW   (CH*PP)       // 1024
#define MROW (BB*NCH)      // 8192
#define CW   (YW+ZP)       // 2624

// merged-round buffer shapes
#define AK 1600            // A-plane pitch (K)
#define BW 2112            // B-plane / C pitch (1600 + 512)
#define AR 2624            // A-plane rows (1600 + 1024)

typedef unsigned long long u64;
typedef __nv_bfloat16 bf16;

// ---------------- fp32 scratch ----------------
__device__ __align__(256) float gM[ZP*ZP], gM32[ZP*ZP];
__device__ __align__(256) float gN[64*ZP];
__device__ __align__(256) float gT1[ZP*UU];
__device__ __align__(256) float gT2[64*UU];
__device__ __align__(256) float gY[ZP*YW];
__device__ __align__(256) float gV[(size_t)XCW*ZP];
__device__ __align__(256) float gNY[64*YW];
__device__ __align__(256) float gWcat[(size_t)ZP*CW];
__device__ __align__(256) float gHcat[(size_t)XCW*CW];
__device__ __align__(256) float gXC[(size_t)MROW*CW];
__device__ __align__(256) float gCR[(size_t)AR*BW];

// ---------------- bf16 split planes ----------------
__device__ __align__(256) bf16 gAh[(size_t)AR*AK], gAl[(size_t)AR*AK];
__device__ __align__(256) bf16 gBh[(size_t)AK*BW], gBl[(size_t)AK*BW];
__device__ __align__(256) bf16 ghh[(size_t)XCW*CW], ghl[(size_t)XCW*CW];
__device__ __align__(256) bf16 gwh[(size_t)ZP*CW],  gwl[(size_t)ZP*CW];
__device__ __align__(256) bf16 gxh[(size_t)MROW*XCW], gxl[(size_t)MROW*XCW];
__device__ __align__(256) bf16 gz0h[BB*ZP], gz0l[BB*ZP], gz1h[BB*ZP], gz1l[BB*ZP];

// ================= shared PTX helpers =================
__device__ __forceinline__ uint32_t bfpack(float x, float y) {  // lo=x, hi=y
    uint32_t r;
    asm("cvt.rn.bf16x2.f32 %0, %1, %2;" : "=r"(r) : "f"(y), "f"(x));
    return r;
}
__device__ __forceinline__ void ldsm4(uint32_t& r0, uint32_t& r1,
                                      uint32_t& r2, uint32_t& r3, uint32_t a) {
    asm volatile("ldmatrix.sync.aligned.m8n8.x4.shared.b16 {%0,%1,%2,%3}, [%4];"
                 : "=r"(r0), "=r"(r1), "=r"(r2), "=r"(r3) : "r"(a));
}
__device__ __forceinline__ void ldsm4t(uint32_t& r0, uint32_t& r1,
                                       uint32_t& r2, uint32_t& r3, uint32_t a) {
    asm volatile("ldmatrix.sync.aligned.m8n8.x4.trans.shared.b16 {%0,%1,%2,%3}, [%4];"
                 : "=r"(r0), "=r"(r1), "=r"(r2), "=r"(r3) : "r"(a));
}
__device__ __forceinline__ void mma16816(float* c, const uint32_t* a, const uint32_t* b) {
    asm volatile("mma.sync.aligned.m16n8k16.row.col.f32.bf16.bf16.f32 "
                 "{%0,%1,%2,%3}, {%4,%5,%6,%7}, {%8,%9}, {%0,%1,%2,%3};"
                 : "+f"(c[0]), "+f"(c[1]), "+f"(c[2]), "+f"(c[3])
                 : "r"(a[0]), "r"(a[1]), "r"(a[2]), "r"(a[3]),
                   "r"(b[0]), "r"(b[1]));
}
__device__ __forceinline__ void cpa16(uint32_t d, const void* g, int bytes) {
    asm volatile("cp.async.cg.shared.global [%0], [%1], 16, %2;"
                 :: "r"(d), "l"(g), "r"(bytes));
}
__device__ __forceinline__ void cpcommit() { asm volatile("cp.async.commit_group;"); }
template<int n> __device__ __forceinline__ void cpwait() {
    asm volatile("cp.async.wait_group %0;" :: "n"(n));
}

// ================= fast path: pre-split bf16 GEMM =================
#define S2   4
#define AROW 80
#define BROW 272
#define A_T  (128*AROW)
#define B_T  (32*BROW)
#define SLOT (2*A_T + 2*B_T)
#define GS2  (S2*SLOT)

__device__ __forceinline__ void issue_stage(
    uint32_t sb, int s, int m0, int n0, int M, int N, int lda, int ldb,
    const bf16* __restrict__ Ah, const bf16* __restrict__ Al,
    const bf16* __restrict__ Bh, const bf16* __restrict__ Bl, int tid)
{
    const int k0 = s * 32;
    const uint32_t sl = sb + (uint32_t)((s % S2) * SLOT);
#pragma unroll
    for (int q = 0; q < 2; ++q) {
        int c = tid + q * 256;
        int m = c >> 2, kc = c & 3;
        int row = m0 + m;
        int bytes = (row < M) ? 16 : 0;
        int rs = bytes ? row : 0;
        const bf16* s1 = Ah + (size_t)rs * lda + k0 + kc * 8;
        const bf16* s2 = Al + (size_t)rs * lda + k0 + kc * 8;
        cpa16(sl + m * AROW + kc * 16, s1, bytes);
        cpa16(sl + A_T + m * AROW + kc * 16, s2, bytes);
    }
#pragma unroll
    for (int q = 0; q < 2; ++q) {
        int c = tid + q * 256;
        int k = c >> 4, nc = c & 15;
        int col = n0 + nc * 8;
        int bytes = (col < N) ? 16 : 0;
        int cs = bytes ? col : 0;
        const bf16* s1 = Bh + (size_t)(k0 + k) * ldb + cs;
        const bf16* s2 = Bl + (size_t)(k0 + k) * ldb + cs;
        cpa16(sl + 2 * A_T + k * BROW + nc * 16, s1, bytes);
        cpa16(sl + 2 * A_T + B_T + k * BROW + nc * 16, s2, bytes);
    }
    cpcommit();
}

// Optional fused split output: if oh != null, columns >= ocol0 of C are also
// written as bf16 hi/lo planes at (row, col - ocol0) with pitch opitch.
__global__ void __launch_bounds__(256, 1) gemm_bf(
    const bf16* __restrict__ Ah, const bf16* __restrict__ Al, int lda,
    const bf16* __restrict__ Bh, const bf16* __restrict__ Bl, int ldb,
    float* __restrict__ C, int ldc, int M, int N, int K, int accum,
    bf16* __restrict__ oh, bf16* __restrict__ ol, int opitch, int ocol0)
{
    extern __shared__ __align__(16) char smem[];
    const uint32_t sb = (uint32_t)__cvta_generic_to_shared(smem);
    const int tid  = threadIdx.x;
    const int wid  = tid >> 5;
    const int lane = tid & 31;
    const int m0 = blockIdx.y * 128;
    const int n0 = blockIdx.x * 128;
    const int wm = (wid >> 2) * 64;
    const int wn = (wid & 3) * 32;

    float acc[4][4][4];
#pragma unroll
    for (int mi = 0; mi < 4; ++mi)
#pragma unroll
        for (int ni = 0; ni < 4; ++ni)
#pragma unroll
            for (int r = 0; r < 4; ++r) acc[mi][ni][r] = 0.f;

    const int nk = K / 32;
    const int pro = (S2 - 1 < nk) ? S2 - 1 : nk;
    for (int s = 0; s < pro; ++s)
        issue_stage(sb, s, m0, n0, M, N, lda, ldb, Ah, Al, Bh, Bl, tid);

    const uint32_t a_lrow = (uint32_t)(lane & 15);
    const uint32_t a_lchk = (uint32_t)(lane >> 4);
    const uint32_t b_krow = (uint32_t)(lane & 15);
    const uint32_t b_ncol = (uint32_t)((lane >> 4) * 8);

    for (int s = 0; s < nk; ++s) {
        cpwait<S2 - 2>();
        __syncthreads();
        if (s + S2 - 1 < nk)
            issue_stage(sb, s + S2 - 1, m0, n0, M, N, lda, ldb, Ah, Al, Bh, Bl, tid);

        const uint32_t base = sb + (uint32_t)((s % S2) * SLOT);
#pragma unroll
        for (int kk = 0; kk < 2; ++kk) {
            uint32_t ah[4][4], al[4][4], bh[4][2], bl[4][2];
#pragma unroll
            for (int mi = 0; mi < 4; ++mi) {
                uint32_t off = (uint32_t)(wm + mi * 16 + a_lrow) * AROW
                             + (uint32_t)(kk * 2 + a_lchk) * 16;
                ldsm4(ah[mi][0], ah[mi][1], ah[mi][2], ah[mi][3], base + off);
                ldsm4(al[mi][0], al[mi][1], al[mi][2], al[mi][3], base + A_T + off);
            }
#pragma unroll
            for (int h = 0; h < 2; ++h) {
                uint32_t off = (uint32_t)(kk * 16 + b_krow) * BROW
                             + (uint32_t)(wn + h * 16 + b_ncol) * 2;
                uint32_t t0, t1, t2, t3;
                ldsm4t(t0, t1, t2, t3, base + 2 * A_T + off);
                bh[2*h][0] = t0; bh[2*h][1] = t1; bh[2*h+1][0] = t2; bh[2*h+1][1] = t3;
                ldsm4t(t0, t1, t2, t3, base + 2 * A_T + B_T + off);
                bl[2*h][0] = t0; bl[2*h][1] = t1; bl[2*h+1][0] = t2; bl[2*h+1][1] = t3;
            }
#pragma unroll
            for (int mi = 0; mi < 4; ++mi)
#pragma unroll
                for (int ni = 0; ni < 4; ++ni) {
                    mma16816(acc[mi][ni], ah[mi], bh[ni]);
                    mma16816(acc[mi][ni], ah[mi], bl[ni]);
                    mma16816(acc[mi][ni], al[mi], bh[ni]);
                }
        }
    }

    // epilogue (+ optional fused bf16 split)
#pragma unroll
    for (int mi = 0; mi < 4; ++mi) {
        int r0 = m0 + wm + mi * 16 + (lane >> 2);
        int r1 = r0 + 8;
#pragma unroll
        for (int ni = 0; ni < 4; ++ni) {
            int cc = n0 + wn + ni * 8 + (lane & 3) * 2;
            if (cc < N) {
#pragma unroll
                for (int hh2 = 0; hh2 < 2; ++hh2) {
                    int row = hh2 ? r1 : r0;
                    if (row < M) {
                        float vx = acc[mi][ni][hh2 * 2];
                        float vy = acc[mi][ni][hh2 * 2 + 1];
                        float2* p = reinterpret_cast<float2*>(&C[(size_t)row * ldc + cc]);
                        if (accum) { float2 v = *p; vx += v.x; vy += v.y; }
                        *p = make_float2(vx, vy);
                        if (oh && cc >= ocol0) {
                            float hx = __bfloat162float(__float2bfloat16(vx));
                            float hy = __bfloat162float(__float2bfloat16(vy));
                            size_t oidx = (size_t)row * opitch + (cc - ocol0);
                            *reinterpret_cast<uint32_t*>(oh + oidx) = bfpack(vx, vy);
                            *reinterpret_cast<uint32_t*>(ol + oidx) = bfpack(vx - hx, vy - hy);
                        }
                    }
                }
            }
        }
    }
}

// ================= slow path: fp32-input GEMM (small builds) ==
#define TBM 128
#define TBN 128
#define TBK 32
#define ROWB 80
#define TILEB (128*ROWB)
#define BUFB (4*TILEB)
#define GSMEM (2*BUFB)

__device__ __forceinline__ void ldg_tiles(
    const float* __restrict__ A, int lda, int M, int m0,
    const float* __restrict__ B, int ldb, int N, int n0,
    int k0, int smr, int kh, float4 ra[4], float rb[16])
{
    const float4 z4 = make_float4(0.f, 0.f, 0.f, 0.f);
    if (m0 + smr < M) {
        const float* ap = A + (size_t)(m0 + smr) * lda + k0 + kh;
#pragma unroll
        for (int j = 0; j < 4; ++j)
            ra[j] = *reinterpret_cast<const float4*>(ap + 4 * j);
    } else {
#pragma unroll
        for (int j = 0; j < 4; ++j) ra[j] = z4;
    }
    if (n0 + smr < N) {
        const float* bp = B + (size_t)(k0 + kh) * ldb + (n0 + smr);
#pragma unroll
        for (int j = 0; j < 16; ++j) rb[j] = bp[(size_t)j * ldb];
    } else {
#pragma unroll
        for (int j = 0; j < 16; ++j) rb[j] = 0.f;
    }
}
__device__ __forceinline__ void split8(const float* v, uint32_t* hw, uint32_t* lw) {
#pragma unroll
    for (int j = 0; j < 8; ++j) {
        float x = v[2 * j], y = v[2 * j + 1];
        float hx = __bfloat162float(__float2bfloat16(x));
        float hy = __bfloat162float(__float2bfloat16(y));
        hw[j] = bfpack(x, y);
        lw[j] = bfpack(x - hx, y - hy);
    }
}
__device__ __forceinline__ void sts_tiles(char* smem, int buf, int smr, int kh,
                                          const float4 ra[4], const float rb[16])
{
    char* base = smem + buf * BUFB;
    uint32_t hw[8], lw[8];
    float av[16];
#pragma unroll
    for (int j = 0; j < 4; ++j) {
        av[4*j] = ra[j].x; av[4*j+1] = ra[j].y; av[4*j+2] = ra[j].z; av[4*j+3] = ra[j].w;
    }
    split8(av, hw, lw);
    {
        char* d = base + smr * ROWB + kh * 2;
        *reinterpret_cast<uint4*>(d)      = make_uint4(hw[0], hw[1], hw[2], hw[3]);
        *reinterpret_cast<uint4*>(d + 16) = make_uint4(hw[4], hw[5], hw[6], hw[7]);
        char* d2 = d + TILEB;
        *reinterpret_cast<uint4*>(d2)      = make_uint4(lw[0], lw[1], lw[2], lw[3]);
        *reinterpret_cast<uint4*>(d2 + 16) = make_uint4(lw[4], lw[5], lw[6], lw[7]);
    }
    split8(rb, hw, lw);
    {
        char* d = base + 2 * TILEB + smr * ROWB + kh * 2;
        *reinterpret_cast<uint4*>(d)      = make_uint4(hw[0], hw[1], hw[2], hw[3]);
        *reinterpret_cast<uint4*>(d + 16) = make_uint4(hw[4], hw[5], hw[6], hw[7]);
        char* d2 = d + TILEB;
        *reinterpret_cast<uint4*>(d2)      = make_uint4(lw[0], lw[1], lw[2], lw[3]);
        *reinterpret_cast<uint4*>(d2 + 16) = make_uint4(lw[4], lw[5], lw[6], lw[7]);
    }
}

__global__ void __launch_bounds__(256, 1) tcgemm_k(
    const float* __restrict__ A, int lda,
    const float* __restrict__ B, int ldb,
    float* __restrict__ C, int ldc,
    int M, int N, int K, int accum)
{
    extern __shared__ __align__(16) char smem[];
    const uint32_t sb = (uint32_t)__cvta_generic_to_shared(smem);
    const int tid  = threadIdx.x;
    const int wid  = tid >> 5;
    const int lane = tid & 31;
    const int m0 = blockIdx.y * TBM;
    const int n0 = blockIdx.x * TBN;
    const int wm = (wid >> 2) * 64;
    const int wn = (wid & 3) * 32;
    const int smr = tid >> 1;
    const int kh  = (tid & 1) * 16;

    float acc[4][4][4];
#pragma unroll
    for (int mi = 0; mi < 4; ++mi)
#pragma unroll
        for (int ni = 0; ni < 4; ++ni)
#pragma unroll
            for (int r = 0; r < 4; ++r) acc[mi][ni][r] = 0.f;

    const uint32_t a_lrow = (uint32_t)(lane & 15);
    const uint32_t a_lchk = (uint32_t)(lane >> 4);
    const uint32_t b_lrow = (uint32_t)(((lane >> 4) << 3) + (lane & 7));
    const uint32_t b_lchk = (uint32_t)((lane >> 3) & 1);

    const int nk = K / TBK;
    float4 ra[4]; float rb[16];
    ldg_tiles(A, lda, M, m0, B, ldb, N, n0, 0, smr, kh, ra, rb);
    sts_tiles(smem, 0, smr, kh, ra, rb);
    __syncthreads();

    for (int s = 0; s < nk; ++s) {
        if (s + 1 < nk)
            ldg_tiles(A, lda, M, m0, B, ldb, N, n0, (s + 1) * TBK, smr, kh, ra, rb);
        const uint32_t base = sb + (uint32_t)((s & 1) * BUFB);
#pragma unroll
        for (int kk = 0; kk < 2; ++kk) {
            uint32_t ah[4][4], al[4][4], bh[4][2], bl[4][2];
#pragma unroll
            for (int mi = 0; mi < 4; ++mi) {
                uint32_t off = (uint32_t)(wm + mi * 16 + a_lrow) * ROWB
                             + (uint32_t)(kk * 2 + a_lchk) * 16;
                ldsm4(ah[mi][0], ah[mi][1], ah[mi][2], ah[mi][3], base + off);
                ldsm4(al[mi][0], al[mi][1], al[mi][2], al[mi][3], base + TILEB + off);
            }
#pragma unroll
            for (int h = 0; h < 2; ++h) {
                uint32_t off = (uint32_t)(wn + h * 16 + b_lrow) * ROWB
                             + (uint32_t)(kk * 2 + b_lchk) * 16;
                uint32_t t0, t1, t2, t3;
                ldsm4(t0, t1, t2, t3, base + 2 * TILEB + off);
                bh[2*h][0] = t0; bh[2*h][1] = t1; bh[2*h+1][0] = t2; bh[2*h+1][1] = t3;
                ldsm4(t0, t1, t2, t3, base + 3 * TILEB + off);
                bl[2*h][0] = t0; bl[2*h][1] = t1; bl[2*h+1][0] = t2; bl[2*h+1][1] = t3;
            }
#pragma unroll
            for (int mi = 0; mi < 4; ++mi)
#pragma unroll
                for (int ni = 0; ni < 4; ++ni) {
                    mma16816(acc[mi][ni], ah[mi], bh[ni]);
                    mma16816(acc[mi][ni], ah[mi], bl[ni]);
                    mma16816(acc[mi][ni], al[mi], bh[ni]);
                }
        }
        __syncthreads();
        if (s + 1 < nk) {
            sts_tiles(smem, (s + 1) & 1, smr, kh, ra, rb);
            __syncthreads();
        }
    }
#pragma unroll
    for (int mi = 0; mi < 4; ++mi) {
        int r0 = m0 + wm + mi * 16 + (lane >> 2);
        int r1 = r0 + 8;
#pragma unroll
        for (int ni = 0; ni < 4; ++ni) {
            int cc = n0 + wn + ni * 8 + (lane & 3) * 2;
            if (cc < N) {
                if (r0 < M) {
                    float2* p = reinterpret_cast<float2*>(&C[(size_t)r0 * ldc + cc]);
                    float2 v = accum ? *p : make_float2(0.f, 0.f);
                    v.x += acc[mi][ni][0]; v.y += acc[mi][ni][1];
                    *p = v;
                }
                if (r1 < M) {
                    float2* p = reinterpret_cast<float2*>(&C[(size_t)r1 * ldc + cc]);
                    float2 v = accum ? *p : make_float2(0.f, 0.f);
                    v.x += acc[mi][ni][2]; v.y += acc[mi][ni][3];
                    *p = v;
                }
            }
        }
    }
}

// ---------------- small helper kernels ----------------
__global__ void kzero(float* p, int n) {
    int i = blockIdx.x * blockDim.x + threadIdx.x;
    if (i < n) p[i] = 0.f;
}
__global__ void kcopy(float* dst, int ldd, const float* src, int lds, int rows, int cols) {
    int i = blockIdx.x * blockDim.x + threadIdx.x;
    if (i >= rows * cols) return;
    int r = i / cols, c = i - r * cols;
    dst[(size_t)r * ldd + c] = src[(size_t)r * lds + c];
}
__global__ void kaddb(float* dst, int ldd, const float* src, int lds, int rows, int cols) {
    int i = blockIdx.x * blockDim.x + threadIdx.x;
    if (i >= rows * cols) return;
    int r = i / cols, c = i - r * cols;
    dst[(size_t)r * ldd + c] += src[(size_t)r * lds + c];
}
__global__ void kvadd2(float* dst, const float* a, const float* b, int n) {
    int i = blockIdx.x * blockDim.x + threadIdx.x;
    if (i < n) dst[i] = a[i] + b[i];
}
__global__ void kvaddrow(float* dst, const float* src, int n) {
    int i = blockIdx.x * blockDim.x + threadIdx.x;
    if (i < n) dst[i] += src[i];
}
__global__ void kdiag(float* M) {
    int i = threadIdx.x;
    if (i < PP) M[(size_t)(1536 + i) * ZP + 1536 + i] += 1.f;
    if (i == PP) M[(size_t)HOM * ZP + HOM] += 1.f;
}
__global__ void khbuild_y(float* Hcat, const float* NY, const float* Nm) {
    int idx = blockIdx.x * blockDim.x + threadIdx.x;
    if (idx >= XCW * YW) return;
    int row = idx >> 10, col = idx & 1023;
    int i = row >> 6, f = row & 63;
    int j = col >> 5, p = col & 31;
    float v = 0.f;
    if (j == i)      v = Nm[(size_t)f * ZP + 1536 + p];
    else if (j > i)  v = NY[(size_t)f * YW + (j - i - 1) * PP + p];
    Hcat[(size_t)row * CW + col] = v;
}
__global__ void kqrev(float* Hcat, const float* V) {
    int idx = blockIdx.x * blockDim.x + threadIdx.x;
    if (idx >= XCW * ZP) return;
    int row = idx / ZP, col = idx - row * ZP;
    int i = row >> 6, f = row & 63;
    Hcat[(size_t)row * CW + YW + col] = V[(size_t)((31 - i) * 64 + f) * ZP + col];
}
__global__ void kout(float* out, const float* XC) {
    int i = blockIdx.x * blockDim.x + threadIdx.x;
    if (i >= BB * TT * PP) return;
    int b = i / (TT * PP), r = i - b * (TT * PP);
    int t = r >> 5, p = r & 31;
    int c = t >> 5, j = t & 31;
    out[i] = XC[((size_t)b * NCH + c) * CW + j * PP + p];
}
// strided fp32 -> strided bf16 hi/lo planes
__global__ void ksplitP(const float* __restrict__ src, int lds,
                        bf16* __restrict__ hi, bf16* __restrict__ lo, int ldd,
                        int rows, int cols) {
    int i = blockIdx.x * blockDim.x + threadIdx.x;
    if (i >= rows * cols) return;
    int r = i / cols, c = i - r * cols;
    float v = src[(size_t)r * lds + c];
    bf16 h = __float2bfloat16(v);
    hi[(size_t)r * ldd + c] = h;
    lo[(size_t)r * ldd + c] = __float2bfloat16(v - __bfloat162float(h));
}
// init z-state planes: z0 = e_HOM
__global__ void kzplanes(bf16* h, bf16* l) {
    int i = blockIdx.x * blockDim.x + threadIdx.x;
    if (i >= BB * ZP) return;
    int c = i % ZP;
    h[i] = __float2bfloat16((c == HOM) ? 1.f : 0.f);
    l[i] = __float2bfloat16(0.f);
}

// ---------------- host ----------------
static void gemm(const float* A, int lda, const float* B, int ldb,
                 float* C, int ldc, int M, int N, int K, int acc)
{
    dim3 g((unsigned)((N + TBN - 1) / TBN), (unsigned)((M + TBM - 1) / TBM));
    tcgemm_k<<<g, 256, GSMEM>>>(A, lda, B, ldb, C, ldc, M, N, K, acc);
}
static void gemmF(const bf16* Ah, const bf16* Al, int lda,
                  const bf16* Bh, const bf16* Bl, int ldb,
                  float* C, int ldc, int M, int N, int K, int acc,
                  bf16* oh = nullptr, bf16* ol = nullptr, int opitch = 0, int ocol0 = 0)
{
    dim3 g((unsigned)((N + 127) / 128), (unsigned)((M + 127) / 128));
    gemm_bf<<<g, 256, GS2>>>(Ah, Al, lda, Bh, Bl, ldb, C, ldc, M, N, K, acc,
                             oh, ol, opitch, ocol0);
}
#define L1D(n) (((n) + 255) / 256), 256
static void splitP(const float* src, int lds, bf16* hi, bf16* lo, int ldd,
                   int rows, int cols) {
    ksplitP<<<L1D(rows * cols)>>>(src, lds, hi, lo, ldd, rows, cols);
}

extern "C" void kernel_launch(void* const* d_in, const int* in_sizes, int n_in,
                              void* d_out, int out_size)
{
    const float* x    = (const float*)d_in[0];
    const float* WA   = (const float*)d_in[1];
    const float* bA   = (const float*)d_in[2];
    const float* WB0  = (const float*)d_in[3];
    const float* bB0  = (const float*)d_in[4];
    const float* WBr  = (const float*)d_in[5];
    const float* bBr  = (const float*)d_in[6];
    const float* WC   = (const float*)d_in[7];
    const float* bC   = (const float*)d_in[8];
    const float* Wout = (const float*)d_in[9];
    const float* bout = (const float*)d_in[10];
    float* out = (float*)d_out;

    static int attr_done = 0;
    if (!attr_done) {
        cudaFuncSetAttribute(tcgemm_k, cudaFuncAttributeMaxDynamicSharedMemorySize, GSMEM);
        cudaFuncSetAttribute(gemm_bf,  cudaFuncAttributeMaxDynamicSharedMemorySize, GS2);
        attr_done = 1;
    }

    float *M_, *M32_, *N_, *T1_, *T2_, *Y_, *V_, *NY_, *Wcat_, *Hcat_, *XC_, *CR_;
    cudaGetSymbolAddress((void**)&M_,   gM);    cudaGetSymbolAddress((void**)&M32_, gM32);
    cudaGetSymbolAddress((void**)&N_,   gN);    cudaGetSymbolAddress((void**)&T1_,  gT1);
    cudaGetSymbolAddress((void**)&T2_,  gT2);   cudaGetSymbolAddress((void**)&Y_,   gY);
    cudaGetSymbolAddress((void**)&V_,   gV);    cudaGetSymbolAddress((void**)&NY_,  gNY);
    cudaGetSymbolAddress((void**)&Wcat_, gWcat); cudaGetSymbolAddress((void**)&Hcat_, gHcat);
    cudaGetSymbolAddress((void**)&XC_,  gXC);   cudaGetSymbolAddress((void**)&CR_,  gCR);

    bf16 *Aph, *Apl_, *Bph, *Bpl_, *hh, *hl, *wh, *wl, *xh, *xl;
    bf16 *z0h, *z0l, *z1h, *z1l;
    cudaGetSymbolAddress((void**)&Aph,  gAh);   cudaGetSymbolAddress((void**)&Apl_, gAl);
    cudaGetSymbolAddress((void**)&Bph,  gBh);   cudaGetSymbolAddress((void**)&Bpl_, gBl);
    cudaGetSymbolAddress((void**)&hh,   ghh);   cudaGetSymbolAddress((void**)&hl,   ghl);
    cudaGetSymbolAddress((void**)&wh,   gwh);   cudaGetSymbolAddress((void**)&wl,   gwl);
    cudaGetSymbolAddress((void**)&xh,   gxh);   cudaGetSymbolAddress((void**)&xl,   gxl);
    cudaGetSymbolAddress((void**)&z0h,  gz0h);  cudaGetSymbolAddress((void**)&z0l,  gz0l);
    cudaGetSymbolAddress((void**)&z1h,  gz1h);  cudaGetSymbolAddress((void**)&z1l,  gz1l);

    const int W2 = UU * UU;

    // ---- build M (step matrix) and N (input matrix) — slow path ----
    kzero<<<L1D(ZP*ZP)>>>(M_, ZP*ZP);
    kzero<<<L1D(64*ZP)>>>(N_, 64*ZP);

    kcopy<<<L1D(UU*UU)>>>(M_,                   ZP, WA,          UU, UU, UU);
    kcopy<<<L1D(PP*UU)>>>(M_ + (size_t)1536*ZP, ZP, WB0 + 64*UU, UU, PP, UU);
    kvadd2<<<L1D(UU)>>>(M_ + (size_t)HOM*ZP, bA, bB0, UU);
    kcopy<<<L1D(64*UU)>>>(N_,                   ZP, WB0,         UU, 64, UU);

    gemm(M_, ZP, WC, UU, T1_, UU, ZP, UU, UU, 0);
    kvaddrow<<<L1D(UU)>>>(T1_ + (size_t)HOM*UU, bC, UU);
    gemm(T1_, UU, WBr, UU, M_ + 512, ZP, ZP, UU, UU, 0);
    kaddb<<<L1D(UU*UU)>>>(M_ + (size_t)512*ZP + 512, ZP, WA + W2, UU, UU, UU);
    kvaddrow<<<L1D(UU)>>>(M_ + (size_t)HOM*ZP + 512, bA + UU, UU);
    kvaddrow<<<L1D(UU)>>>(M_ + (size_t)HOM*ZP + 512, bBr, UU);
    gemm(N_, ZP, WC, UU, T2_, UU, 64, UU, UU, 0);
    gemm(T2_, UU, WBr, UU, N_ + 512, ZP, 64, UU, UU, 0);

    gemm(M_ + 512, ZP, WC + W2, UU, T1_, UU, ZP, UU, UU, 0);
    kvaddrow<<<L1D(UU)>>>(T1_ + (size_t)HOM*UU, bC + UU, UU);
    gemm(T1_, UU, WBr + W2, UU, M_ + 1024, ZP, ZP, UU, UU, 0);
    kaddb<<<L1D(UU*UU)>>>(M_ + (size_t)1024*ZP + 1024, ZP, WA + 2*W2, UU, UU, UU);
    kvaddrow<<<L1D(UU)>>>(M_ + (size_t)HOM*ZP + 1024, bA + 2*UU, UU);
    kvaddrow<<<L1D(UU)>>>(M_ + (size_t)HOM*ZP + 1024, bBr + UU, UU);
    gemm(N_ + 512, ZP, WC + W2, UU, T2_, UU, 64, UU, UU, 0);
    gemm(T2_, UU, WBr + W2, UU, N_ + 1024, ZP, 64, UU, UU, 0);

    gemm(M_ + 1024, ZP, WC + 2*W2, UU, T1_, UU, ZP, UU, UU, 0);
    kvaddrow<<<L1D(UU)>>>(T1_ + (size_t)HOM*UU, bC + 2*UU, UU);
    gemm(T1_, UU, Wout, PP, M_ + 1536, ZP, ZP, PP, UU, 0);
    kvaddrow<<<L1D(PP)>>>(M_ + (size_t)HOM*ZP + 1536, bout, PP);
    kcopy<<<L1D(ZP*PP)>>>(Y_, YW, M_ + 1536, ZP, ZP, PP);   // D seed (pre-identity)
    kdiag<<<1, 64>>>(M_);
    gemm(N_ + 1024, ZP, WC + 2*W2, UU, T2_, UU, 64, UU, UU, 0);
    gemm(T2_, UU, Wout, PP, N_ + 1536, ZP, 64, PP, UU, 0);
    kcopy<<<L1D(64*ZP)>>>(V_, ZP, N_, ZP, 64, ZP);          // V block 0 = N (fp32)

    // ---- merged doubling rounds: one GEMM computes M^{2p}, Ynext, Vnext ----
    // A planes = [M^p (1600 rows); V prefix], B planes = [M^p | Y prefix]
    splitP(M_, ZP, Aph, Apl_, AK, 1600, 1600);
    splitP(N_, ZP, Aph + (size_t)1600*AK, Apl_ + (size_t)1600*AK, AK, 64, 1600);
    splitP(M_, ZP, Bph, Bpl_, BW, 1600, 1600);
    splitP(Y_, YW, Bph + 1600, Bpl_ + 1600, BW, 1600, 32);

    for (int d = 0; d < 5; ++d) {
        const int w = 32 << d, r = 64 << d;
        gemmF(Aph, Apl_, AK, Bph, Bpl_, BW, CR_, BW, 1600 + r, 1600 + w, 1600, 0);
        // fp32 extracts (needed later for Hcat/Wcat builds)
        kcopy<<<L1D(1600*w)>>>(Y_ + w, YW, CR_ + 1600, BW, 1600, w);
        kcopy<<<L1D(r*1600)>>>(V_ + (size_t)r*ZP, ZP, CR_ + (size_t)1600*BW, BW, r, 1600);
        if (d < 4) {
            splitP(CR_, BW, Aph, Apl_, AK, 1600, 1600);                 // new power -> A top
            splitP(CR_, BW, Bph, Bpl_, BW, 1600, 1600);                 // new power -> B left
            splitP(CR_ + (size_t)1600*BW, BW,
                   Aph + (size_t)(1600 + r)*AK, Apl_ + (size_t)(1600 + r)*AK,
                   AK, r, 1600);                                        // V append
            splitP(CR_ + 1600, BW, Bph + 1600 + w, Bpl_ + 1600 + w, BW, 1600, w); // Y append
        } else {
            kcopy<<<L1D(1600*1600)>>>(M32_, ZP, CR_, BW, 1600, 1600);
        }
    }

    // ---- Hcat = [Hy | Q], Wcat = [Ystack | M32] ----
    gemm(N_, ZP, Y_, YW, NY_, YW, 64, YW, ZP, 0);
    khbuild_y<<<L1D(XCW*YW)>>>(Hcat_, NY_, N_);
    kqrev<<<L1D(XCW*ZP)>>>(Hcat_, V_);
    kcopy<<<L1D(ZP*YW)>>>(Wcat_,      CW, Y_,   YW, ZP, YW);
    kcopy<<<L1D(ZP*ZP)>>>(Wcat_ + YW, CW, M32_, ZP, ZP, ZP);
    splitP(Hcat_, CW, hh, hl, CW, XCW, CW);
    splitP(Wcat_, CW, wh, wl, CW, ZP, CW);
    splitP(x, XCW, xh, xl, XCW, MROW, XCW);

    // ---- one giant x-driven GEMM: XC = X * Hcat (8192 x 2624 x 2048) ----
    gemmF(xh, xl, XCW, hh, hl, CW, XC_, CW, MROW, CW, XCW, 0);

    // ---- serial z-chain with fused split epilogue (ping-pong plane pairs) ----
    kzplanes<<<L1D(BB*ZP)>>>(z0h, z0l);
    for (int c = 0; c < NCH; ++c) {
        const bf16* ah = (c & 1) ? z1h : z0h;
        const bf16* al = (c & 1) ? z1l : z0l;
        bf16* oh = (c & 1) ? z0h : z1h;
        bf16* ol = (c & 1) ? z0l : z1l;
        gemmF(ah, al, ZP, wh, wl, CW, XC_ + (size_t)c * CW, NCH * CW,
              BB, CW, ZP, 1, oh, ol, ZP, YW);
    }

    // ---- scatter y-part to output ----
    kout<<<L1D(BB*TT*PP)>>>(out, XC_);
}